// round 8
// baseline (speedup 1.0000x reference)
#include <cuda_runtime.h>
#include <cuda_bf16.h>
#include <math.h>
#include <stdint.h>

#define NE 16
#define DIM 512
#define HID 1024
#define MAXT 8192
#define MAXSLOTS (MAXT * 2)

// ---------------- scratch (device globals; no allocation allowed) ----------
__device__ int   g_cnt[NE];
__device__ int   g_cursor[NE];
__device__ int   g_off[NE + 1];
__device__ int   g_tp[NE + 1];
__device__ int   g_tidx[MAXSLOTS];
__device__ float g_tw[MAXSLOTS];
__device__ int   g_slot_token[MAXSLOTS];
__device__ int   g_slot_of[MAXSLOTS];
__device__ __nv_bfloat16 g_hb[(size_t)MAXSLOTS * HID];   // gelu(h) bf16, 32 MB
__device__ float         g_o [(size_t)MAXSLOTS * DIM];   // expert out fp32, 32 MB
__device__ __nv_bfloat16 g_w1b[(size_t)NE * DIM * HID];  // W1 bf16, SAME [E][K][N]
__device__ __nv_bfloat16 g_w2b[(size_t)NE * HID * DIM];  // W2 bf16, SAME [E][K][N]

// ---------------- PTX helpers ------------------------------------------------
__device__ __forceinline__ uint32_t smem_u32(const void* p) {
    uint32_t a;
    asm("{ .reg .u64 t; cvta.to.shared.u64 t, %1; cvt.u32.u64 %0, t; }"
        : "=r"(a) : "l"(p));
    return a;
}

#define CP_ASYNC16(dst, src) \
    asm volatile("cp.async.cg.shared.global [%0], [%1], 16;" \
                 :: "r"(dst), "l"(src) : "memory")
#define CP_COMMIT() asm volatile("cp.async.commit_group;" ::: "memory")
#define CP_WAIT2()  asm volatile("cp.async.wait_group 2;"  ::: "memory")

// tf32 mma, operands raw fp32 bit patterns (HW truncates to tf32)
#define MMA_TF32(c, a0, a1, a2, a3, b0, b1) \
    asm volatile("mma.sync.aligned.m16n8k8.row.col.f32.tf32.tf32.f32 " \
                 "{%0,%1,%2,%3}, {%4,%5,%6,%7}, {%8,%9}, {%0,%1,%2,%3};" \
                 : "+f"((c)[0]), "+f"((c)[1]), "+f"((c)[2]), "+f"((c)[3]) \
                 : "r"(a0), "r"(a1), "r"(a2), "r"(a3), "r"(b0), "r"(b1))

// bf16 half of word -> fp32 bit pattern. odd: high half, even: low half.
__device__ __forceinline__ uint32_t bfsel(uint32_t u, int odd) {
    return odd ? (u & 0xFFFF0000u) : (u << 16);
}

// ---------------- small kernels (verified rounds 1-6) -----------------------
__global__ void k_init() { if (threadIdx.x < NE) g_cnt[threadIdx.x] = 0; }

__global__ void k_router(const float* __restrict__ x,
                         const float* __restrict__ Wr,
                         const float* __restrict__ br, int T) {
    int w = (blockIdx.x * blockDim.x + threadIdx.x) >> 5;
    int lane = threadIdx.x & 31;
    if (w >= T) return;
    float acc[NE];
#pragma unroll
    for (int e = 0; e < NE; e++) acc[e] = 0.f;
    const float* xr = x + (size_t)w * DIM;
    for (int d = lane; d < DIM; d += 32) {
        float xv = xr[d];
        const float* wr = Wr + d * NE;
#pragma unroll
        for (int e = 0; e < NE; e++) acc[e] = fmaf(xv, wr[e], acc[e]);
    }
#pragma unroll
    for (int off = 16; off; off >>= 1)
#pragma unroll
        for (int e = 0; e < NE; e++)
            acc[e] += __shfl_xor_sync(0xffffffffu, acc[e], off);
    if (lane == 0) {
#pragma unroll
        for (int e = 0; e < NE; e++) acc[e] += br[e];
        int b0 = 0; float l0 = acc[0];
#pragma unroll
        for (int e = 1; e < NE; e++) if (acc[e] > l0) { l0 = acc[e]; b0 = e; }
        int b1 = -1; float l1 = -3.0e38f;
#pragma unroll
        for (int e = 0; e < NE; e++)
            if (e != b0 && acc[e] > l1) { l1 = acc[e]; b1 = e; }
        float w0 = 1.f / (1.f + expf(l1 - l0));
        g_tidx[2 * w] = b0; g_tidx[2 * w + 1] = b1;
        g_tw[2 * w] = w0;   g_tw[2 * w + 1] = 1.f - w0;
        atomicAdd(&g_cnt[b0], 1);
        atomicAdd(&g_cnt[b1], 1);
    }
}

__global__ void k_scan() {
    if (threadIdx.x == 0) {
        g_off[0] = 0; g_tp[0] = 0;
        for (int e = 0; e < NE; e++) {
            int c = g_cnt[e];
            g_off[e + 1] = g_off[e] + c;
            g_cursor[e] = g_off[e];
            g_tp[e + 1] = g_tp[e] + (c + 127) / 128;
        }
    }
}

__global__ void k_scatter(int T) {
    int i = blockIdx.x * blockDim.x + threadIdx.x;
    if (i >= 2 * T) return;
    int e = g_tidx[i];
    int pos = atomicAdd(&g_cursor[e], 1);
    g_slot_token[pos] = i >> 1;
    g_slot_of[i] = pos;
}

// elementwise fp32 -> bf16, SAME layout (no transpose)
__global__ void k_cvt(const float* __restrict__ W,
                      __nv_bfloat16* __restrict__ Wb, int n4) {
    int i = blockIdx.x * blockDim.x + threadIdx.x;
    if (i >= n4) return;
    float4 v = *(const float4*)(W + (size_t)i * 4);
    __nv_bfloat162 a = __floats2bfloat162_rn(v.x, v.y);
    __nv_bfloat162 b = __floats2bfloat162_rn(v.z, v.w);
    uint2 o;
    o.x = *(uint32_t*)&a;
    o.y = *(uint32_t*)&b;
    *(uint2*)(Wb + (size_t)i * 4) = o;
}

__device__ __forceinline__ float gelu(float v) {
    return 0.5f * v * (1.f + erff(v * 0.70710678118654752f));
}

// ---------------- grouped GEMM: tf32 mma, bf16-in-smem, 3-stage pipeline ----
// FIRST: g_hb = bf16(gelu(gather(x) @ W1b[e] + b1[e])),  N=HID, K=DIM
// else : g_o  = g_hb @ W2b[e] + b2[e],                   N=DIM, K=HID
// A stage (FIRST): fp32, 128 rows x (32 + 4 pad) words, stride 36 (bank=4g+t, CF)
// A stage (else) : bf16, 128 rows x (16 + 4 pad) words, stride 20
//                  (80B rows: 16B-aligned for cp.async; banks 20g+w0 all distinct)
// B stage        : bf16,  32 rows x (64 + 4 pad) words, stride 68 (272B, CF)
template <bool FIRST>
__global__ void __launch_bounds__(256, 2)
k_gemm(const float* __restrict__ Xf,
       const __nv_bfloat16* __restrict__ Bw,
       const float* __restrict__ bias) {
    constexpr int N   = FIRST ? HID : DIM;
    constexpr int K   = FIRST ? DIM : HID;
    constexpr int KT  = K / 32;
    constexpr int NT  = N / 128;
    constexpr int AW  = FIRST ? 36 : 20;      // words per A smem row
    constexpr int A_W = 128 * AW;
    constexpr int B_W = 32 * 68;
    constexpr int ST_W = A_W + B_W;           // stage words
    constexpr uint32_t ST_B = ST_W * 4;       // stage bytes

    extern __shared__ uint32_t dsw[];
    const uint32_t sb = smem_u32(dsw);

    const int tid  = threadIdx.x;
    const int lane = tid & 31;
    const int wid  = tid >> 5;
    const int wm   = (wid & 3) * 32;
    const int wn   = (wid >> 2) * 64;
    const int g    = lane >> 2;
    const int t    = lane & 3;
    const int apar = t & 1;                   // k parity for bf16 A fragments
    const int bpar = g & 1;                   // n parity for bf16 B fragments

    const int total = g_tp[NE] * NT;

    for (int work = blockIdx.x; work < total; work += gridDim.x) {
        const int mt = work / NT;
        const int nt = work - mt * NT;
        int e = 0;
        while (g_tp[e + 1] <= mt) e++;
        const int m0   = g_off[e] + (mt - g_tp[e]) * 128;
        const int mEnd = g_off[e + 1];
        const int n0   = nt * 128;
        const __nv_bfloat16* Be = Bw + (size_t)e * K * N + n0;  // [K][N] bf16

        // -------- loader: k-tile kt (32 k) -> stage s --------
        auto load_tile = [&](int kt, int s) {
            const uint32_t ab = sb + (uint32_t)s * ST_B;
            const uint32_t bb = ab + A_W * 4;
            if (FIRST) {
                // A: gathered x fp32, 128 rows x 8 chunks of 16B (144B rows)
#pragma unroll
                for (int j = 0; j < 4; j++) {
                    int idx = tid + j * 256;
                    int row = idx >> 3, c = idx & 7;
                    int rg = min(m0 + row, mEnd - 1);
                    const float* src = Xf + (size_t)g_slot_token[rg] * K
                                          + kt * 32 + c * 4;
                    CP_ASYNC16(ab + (uint32_t)(row * 144 + c * 16), src);
                }
            } else {
                // A: g_hb bf16, 128 rows x 4 chunks of 16B (80B rows, aligned)
#pragma unroll
                for (int j = 0; j < 2; j++) {
                    int idx = tid + j * 256;
                    int row = idx >> 2, c = idx & 3;
                    int rg = min(m0 + row, mEnd - 1);
                    const char* src = (const char*)g_hb
                        + ((size_t)rg * HID + kt * 32) * 2 + c * 16;
                    CP_ASYNC16(ab + (uint32_t)(row * 80 + c * 16), src);
                }
            }
            // B: bf16 [K][N], 32 k-rows x 16 chunks of 16B (272B rows)
#pragma unroll
            for (int j = 0; j < 2; j++) {
                int idx = tid + j * 256;
                int row = idx >> 4, c = idx & 15;
                const char* src = (const char*)Be
                    + ((size_t)(kt * 32 + row) * N) * 2 + c * 16;
                CP_ASYNC16(bb + (uint32_t)(row * 272 + c * 16), src);
            }
        };

        float acc[2][8][4];
#pragma unroll
        for (int mi = 0; mi < 2; mi++)
#pragma unroll
            for (int ni = 0; ni < 8; ni++)
#pragma unroll
                for (int q = 0; q < 4; q++) acc[mi][ni][q] = 0.f;

        load_tile(0, 0); CP_COMMIT();
        load_tile(1, 1); CP_COMMIT();
        load_tile(2, 2); CP_COMMIT();

        for (int i = 0; i < KT; i++) {
            CP_WAIT2();
            __syncthreads();
            const int s = i % 3;
            const uint32_t* Aw = dsw + (size_t)s * ST_W;
            const uint32_t* Bs = Aw + A_W;
#pragma unroll
            for (int ks = 0; ks < 4; ks++) {
                const int kk = ks * 8;
                uint32_t af[2][4];
#pragma unroll
                for (int mi = 0; mi < 2; mi++) {
                    const int r = wm + mi * 16 + g;
                    if (FIRST) {
                        af[mi][0] = Aw[r * 36 + kk + t];
                        af[mi][1] = Aw[(r + 8) * 36 + kk + t];
                        af[mi][2] = Aw[r * 36 + kk + t + 4];
                        af[mi][3] = Aw[(r + 8) * 36 + kk + t + 4];
                    } else {
                        const int w0 = ks * 4 + (t >> 1);
                        af[mi][0] = bfsel(Aw[r * 20 + w0], apar);
                        af[mi][1] = bfsel(Aw[(r + 8) * 20 + w0], apar);
                        af[mi][2] = bfsel(Aw[r * 20 + w0 + 2], apar);
                        af[mi][3] = bfsel(Aw[(r + 8) * 20 + w0 + 2], apar);
                    }
                }
#pragma unroll
                for (int ni = 0; ni < 8; ni++) {
                    const int cw = (wn >> 1) + ni * 4 + (g >> 1);
                    uint32_t b0 = bfsel(Bs[(kk + t) * 68 + cw], bpar);
                    uint32_t b1 = bfsel(Bs[(kk + t + 4) * 68 + cw], bpar);
                    MMA_TF32(acc[0][ni], af[0][0], af[0][1], af[0][2], af[0][3], b0, b1);
                    MMA_TF32(acc[1][ni], af[1][0], af[1][1], af[1][2], af[1][3], b0, b1);
                }
            }
            __syncthreads();
            if (i + 3 < KT) load_tile(i + 3, s);
            CP_COMMIT();
        }

        // -------- epilogue (mapping verified rounds 2/6) --------
#pragma unroll
        for (int mi = 0; mi < 2; mi++) {
            const int row0 = m0 + wm + mi * 16 + g;
            const int row1 = row0 + 8;
#pragma unroll
            for (int ni = 0; ni < 8; ni++) {
                const int col = n0 + wn + ni * 8 + 2 * t;
                const float2 bb = *(const float2*)(bias + e * N + col);
                float v0 = acc[mi][ni][0] + bb.x;
                float v1 = acc[mi][ni][1] + bb.y;
                float v2 = acc[mi][ni][2] + bb.x;
                float v3 = acc[mi][ni][3] + bb.y;
                if (FIRST) {
                    v0 = gelu(v0); v1 = gelu(v1); v2 = gelu(v2); v3 = gelu(v3);
                    uint32_t p0, p1;  // lo = even col (v0/v2), hi = odd (v1/v3)
                    asm("cvt.rn.bf16x2.f32 %0, %1, %2;" : "=r"(p0) : "f"(v1), "f"(v0));
                    asm("cvt.rn.bf16x2.f32 %0, %1, %2;" : "=r"(p1) : "f"(v3), "f"(v2));
                    if (row0 < mEnd)
                        *(uint32_t*)(g_hb + (size_t)row0 * HID + col) = p0;
                    if (row1 < mEnd)
                        *(uint32_t*)(g_hb + (size_t)row1 * HID + col) = p1;
                } else {
                    if (row0 < mEnd) {
                        float2 o = {v0, v1};
                        *(float2*)(g_o + (size_t)row0 * DIM + col) = o;
                    }
                    if (row1 < mEnd) {
                        float2 o = {v2, v3};
                        *(float2*)(g_o + (size_t)row1 * DIM + col) = o;
                    }
                }
            }
        }
        __syncthreads();   // stages fully consumed before next work's loads
    }
}

// ---------------- combine: y = x + w0*o[s0] + w1*o[s1] ----------------------
__global__ void k_combine(const float* __restrict__ x, float* __restrict__ y,
                          int T) {
    int i = blockIdx.x * blockDim.x + threadIdx.x;
    int total = T * (DIM / 4);
    if (i >= total) return;
    int t = i / (DIM / 4);
    int d = (i - t * (DIM / 4)) * 4;
    float w0 = g_tw[2 * t], w1 = g_tw[2 * t + 1];
    int s0 = g_slot_of[2 * t], s1 = g_slot_of[2 * t + 1];
    float4 xv = *(const float4*)(x + (size_t)t * DIM + d);
    float4 o0 = *(const float4*)(g_o + (size_t)s0 * DIM + d);
    float4 o1 = *(const float4*)(g_o + (size_t)s1 * DIM + d);
    float4 r;
    r.x = xv.x + w0 * o0.x + w1 * o1.x;
    r.y = xv.y + w0 * o0.y + w1 * o1.y;
    r.z = xv.z + w0 * o0.z + w1 * o1.z;
    r.w = xv.w + w0 * o0.w + w1 * o1.w;
    *(float4*)(y + (size_t)t * DIM + d) = r;
}

// ---------------- launch -----------------------------------------------------
#define SMEM1 (3 * (128 * 36 + 32 * 68) * 4)   // 81408
#define SMEM2 (3 * (128 * 20 + 32 * 68) * 4)   // 56832

extern "C" void kernel_launch(void* const* d_in, const int* in_sizes, int n_in,
                              void* d_out, int out_size) {
    const float* x  = (const float*)d_in[0];
    const float* Wr = (const float*)d_in[1];
    const float* br = (const float*)d_in[2];
    const float* W1 = (const float*)d_in[3];
    const float* b1 = (const float*)d_in[4];
    const float* W2 = (const float*)d_in[5];
    const float* b2 = (const float*)d_in[6];
    float* y = (float*)d_out;
    const int T = in_sizes[0] / DIM;

    cudaFuncSetAttribute(k_gemm<true>,  cudaFuncAttributeMaxDynamicSharedMemorySize, SMEM1);
    cudaFuncSetAttribute(k_gemm<false>, cudaFuncAttributeMaxDynamicSharedMemorySize, SMEM2);

    __nv_bfloat16* w1b; cudaGetSymbolAddress((void**)&w1b, g_w1b);
    __nv_bfloat16* w2b; cudaGetSymbolAddress((void**)&w2b, g_w2b);

    k_init<<<1, 32>>>();
    {
        int n4 = NE * DIM * HID / 4;
        k_cvt<<<(n4 + 255) / 256, 256>>>(W1, w1b, n4);
        k_cvt<<<(n4 + 255) / 256, 256>>>(W2, w2b, n4);
    }
    k_router<<<(T + 7) / 8, 256>>>(x, Wr, br, T);
    k_scan<<<1, 32>>>();
    k_scatter<<<(2 * T + 255) / 256, 256>>>(T);

    k_gemm<true ><<<296, 256, SMEM1>>>(x, w1b, b1);
    k_gemm<false><<<296, 256, SMEM2>>>(nullptr, w2b, b2);
    k_combine<<<(T * (DIM / 4) + 255) / 256, 256>>>(x, y, T);
}

// round 9
// speedup vs baseline: 1.4411x; 1.4411x over previous
#include <cuda_runtime.h>
#include <cuda_bf16.h>
#include <math.h>
#include <stdint.h>

#define NE 16
#define DIM 512
#define HID 1024
#define MAXT 8192
#define MAXSLOTS (MAXT * 2)

// ---------------- scratch (device globals; no allocation allowed) ----------
__device__ int   g_cnt[NE];
__device__ int   g_cursor[NE];
__device__ int   g_off[NE + 1];
__device__ int   g_tp[NE + 1];
__device__ int   g_tidx[MAXSLOTS];
__device__ float g_tw[MAXSLOTS];
__device__ int   g_slot_token[MAXSLOTS];
__device__ int   g_slot_of[MAXSLOTS];
__device__ __nv_bfloat16 g_hb[(size_t)MAXSLOTS * HID];   // gelu(h) bf16, 32 MB
__device__ float         g_o [(size_t)MAXSLOTS * DIM];   // expert out fp32, 32 MB
__device__ __nv_bfloat16 g_w1b[(size_t)NE * DIM * HID];  // W1 bf16, SAME [E][K][N]
__device__ __nv_bfloat16 g_w2b[(size_t)NE * HID * DIM];  // W2 bf16, SAME [E][K][N]

// ---------------- PTX helpers ------------------------------------------------
__device__ __forceinline__ uint32_t smem_u32(const void* p) {
    uint32_t a;
    asm("{ .reg .u64 t; cvta.to.shared.u64 t, %1; cvt.u32.u64 %0, t; }"
        : "=r"(a) : "l"(p));
    return a;
}

#define CP_ASYNC16(dst, src) \
    asm volatile("cp.async.cg.shared.global [%0], [%1], 16;" \
                 :: "r"(dst), "l"(src) : "memory")
#define CP_COMMIT() asm volatile("cp.async.commit_group;" ::: "memory")
#define CP_WAIT2()  asm volatile("cp.async.wait_group 2;"  ::: "memory")

#define MMA_BF16(c, a0, a1, a2, a3, b0, b1) \
    asm volatile("mma.sync.aligned.m16n8k16.row.col.f32.bf16.bf16.f32 " \
                 "{%0,%1,%2,%3}, {%4,%5,%6,%7}, {%8,%9}, {%0,%1,%2,%3};" \
                 : "+f"((c)[0]), "+f"((c)[1]), "+f"((c)[2]), "+f"((c)[3]) \
                 : "r"(a0), "r"(a1), "r"(a2), "r"(a3), "r"(b0), "r"(b1))

// pack two fp32 -> bf16x2 {lo = v.x (even k), hi = v.y (odd k)}
// (operand order verified by rounds 7/8 passing epilogue: src0 = hi, src1 = lo)
__device__ __forceinline__ uint32_t cvtpack(float2 v) {
    uint32_t d;
    asm("cvt.rn.bf16x2.f32 %0, %1, %2;" : "=r"(d) : "f"(v.y), "f"(v.x));
    return d;
}

__device__ __forceinline__ uint32_t prmt(uint32_t a, uint32_t b, uint32_t sel) {
    uint32_t d;
    asm("prmt.b32 %0, %1, %2, %3;" : "=r"(d) : "r"(a), "r"(b), "r"(sel));
    return d;
}

// ---------------- small kernels ---------------------------------------------
__global__ void k_init() { if (threadIdx.x < NE) g_cnt[threadIdx.x] = 0; }

// router: 4 tokens per warp (amortizes Wr reads 4x)
__global__ void k_router(const float* __restrict__ x,
                         const float* __restrict__ Wr,
                         const float* __restrict__ br, int T) {
    int w    = (blockIdx.x * blockDim.x + threadIdx.x) >> 5;
    int lane = threadIdx.x & 31;
    int t0   = w * 4;
    if (t0 >= T) return;

    float acc[4][NE];
#pragma unroll
    for (int j = 0; j < 4; j++)
#pragma unroll
        for (int e = 0; e < NE; e++) acc[j][e] = 0.f;

    for (int d = lane; d < DIM; d += 32) {
        float xv[4];
#pragma unroll
        for (int j = 0; j < 4; j++)
            xv[j] = (t0 + j < T) ? x[(size_t)(t0 + j) * DIM + d] : 0.f;
        const float* wr = Wr + d * NE;
#pragma unroll
        for (int e = 0; e < NE; e++) {
            float we = wr[e];
#pragma unroll
            for (int j = 0; j < 4; j++)
                acc[j][e] = fmaf(xv[j], we, acc[j][e]);
        }
    }
#pragma unroll
    for (int off = 16; off; off >>= 1)
#pragma unroll
        for (int j = 0; j < 4; j++)
#pragma unroll
            for (int e = 0; e < NE; e++)
                acc[j][e] += __shfl_xor_sync(0xffffffffu, acc[j][e], off);

    if (lane < 4 && t0 + lane < T) {
        const int tok = t0 + lane;
        float l[NE];
#pragma unroll
        for (int e = 0; e < NE; e++) l[e] = acc[lane][e] + br[e];
        int b0 = 0; float l0 = l[0];
#pragma unroll
        for (int e = 1; e < NE; e++) if (l[e] > l0) { l0 = l[e]; b0 = e; }
        int b1 = -1; float l1 = -3.0e38f;
#pragma unroll
        for (int e = 0; e < NE; e++)
            if (e != b0 && l[e] > l1) { l1 = l[e]; b1 = e; }
        float w0 = 1.f / (1.f + expf(l1 - l0));
        g_tidx[2 * tok] = b0; g_tidx[2 * tok + 1] = b1;
        g_tw[2 * tok] = w0;   g_tw[2 * tok + 1] = 1.f - w0;
        atomicAdd(&g_cnt[b0], 1);
        atomicAdd(&g_cnt[b1], 1);
    }
}

__global__ void k_scan() {
    if (threadIdx.x == 0) {
        g_off[0] = 0; g_tp[0] = 0;
        for (int e = 0; e < NE; e++) {
            int c = g_cnt[e];
            g_off[e + 1] = g_off[e] + c;
            g_cursor[e] = g_off[e];
            g_tp[e + 1] = g_tp[e] + (c + 127) / 128;
        }
    }
}

__global__ void k_scatter(int T) {
    int i = blockIdx.x * blockDim.x + threadIdx.x;
    if (i >= 2 * T) return;
    int e = g_tidx[i];
    int pos = atomicAdd(&g_cursor[e], 1);
    g_slot_token[pos] = i >> 1;
    g_slot_of[i] = pos;
}

// elementwise fp32 -> bf16, SAME layout (no transpose)
__global__ void k_cvt(const float* __restrict__ W,
                      __nv_bfloat16* __restrict__ Wb, int n4) {
    int i = blockIdx.x * blockDim.x + threadIdx.x;
    if (i >= n4) return;
    float4 v = *(const float4*)(W + (size_t)i * 4);
    __nv_bfloat162 a = __floats2bfloat162_rn(v.x, v.y);
    __nv_bfloat162 b = __floats2bfloat162_rn(v.z, v.w);
    uint2 o;
    o.x = *(uint32_t*)&a;
    o.y = *(uint32_t*)&b;
    *(uint2*)(Wb + (size_t)i * 4) = o;
}

__device__ __forceinline__ float gelu(float v) {
    return 0.5f * v * (1.f + erff(v * 0.70710678118654752f));
}

// ---------------- grouped GEMM: bf16 mma m16n8k16, 3-stage cp.async ---------
// FIRST: g_hb = bf16(gelu(gather(x) @ W1b[e] + b1[e])),  N=HID, K=DIM
// else : g_o  = g_hb @ W2b[e] + b2[e],                   N=DIM, K=HID
// Smem stages byte-identical to round 8 (hardware-verified loaders):
//   A (FIRST): fp32, 128 x (32+4) words, stride 36 (144B rows)
//   A (else) : bf16, 128 x (16+4) words, stride 20 (80B rows)
//   B        : bf16,  32 x (64+4) words, stride 68 (272B rows)
template <bool FIRST>
__global__ void __launch_bounds__(256, 2)
k_gemm(const float* __restrict__ Xf,
       const __nv_bfloat16* __restrict__ Bw,
       const float* __restrict__ bias) {
    constexpr int N   = FIRST ? HID : DIM;
    constexpr int K   = FIRST ? DIM : HID;
    constexpr int KT  = K / 32;
    constexpr int NT  = N / 128;
    constexpr int AW  = FIRST ? 36 : 20;
    constexpr int A_W = 128 * AW;
    constexpr int B_W = 32 * 68;
    constexpr int ST_W = A_W + B_W;
    constexpr uint32_t ST_B = ST_W * 4;

    extern __shared__ uint32_t dsw[];
    const uint32_t sb = smem_u32(dsw);

    const int tid  = threadIdx.x;
    const int lane = tid & 31;
    const int wid  = tid >> 5;
    const int wm   = (wid & 3) * 32;
    const int wn   = (wid >> 2) * 64;
    const int g    = lane >> 2;
    const int t    = lane & 3;
    const uint32_t psel = (g & 1) ? 0x7632u : 0x5410u;  // n-half select for B prmt

    const int total = g_tp[NE] * NT;

    for (int work = blockIdx.x; work < total; work += gridDim.x) {
        const int mt = work / NT;
        const int nt = work - mt * NT;
        int e = 0;
        while (g_tp[e + 1] <= mt) e++;
        const int m0   = g_off[e] + (mt - g_tp[e]) * 128;
        const int mEnd = g_off[e + 1];
        const int n0   = nt * 128;
        const __nv_bfloat16* Be = Bw + (size_t)e * K * N + n0;

        // -------- loader: identical to round 8 (verified) --------
        auto load_tile = [&](int kt, int s) {
            const uint32_t ab = sb + (uint32_t)s * ST_B;
            const uint32_t bb = ab + A_W * 4;
            if (FIRST) {
#pragma unroll
                for (int j = 0; j < 4; j++) {
                    int idx = tid + j * 256;
                    int row = idx >> 3, c = idx & 7;
                    int rg = min(m0 + row, mEnd - 1);
                    const float* src = Xf + (size_t)g_slot_token[rg] * K
                                          + kt * 32 + c * 4;
                    CP_ASYNC16(ab + (uint32_t)(row * 144 + c * 16), src);
                }
            } else {
#pragma unroll
                for (int j = 0; j < 2; j++) {
                    int idx = tid + j * 256;
                    int row = idx >> 2, c = idx & 3;
                    int rg = min(m0 + row, mEnd - 1);
                    const char* src = (const char*)g_hb
                        + ((size_t)rg * HID + kt * 32) * 2 + c * 16;
                    CP_ASYNC16(ab + (uint32_t)(row * 80 + c * 16), src);
                }
            }
#pragma unroll
            for (int j = 0; j < 2; j++) {
                int idx = tid + j * 256;
                int row = idx >> 4, c = idx & 15;
                const char* src = (const char*)Be
                    + ((size_t)(kt * 32 + row) * N) * 2 + c * 16;
                CP_ASYNC16(bb + (uint32_t)(row * 272 + c * 16), src);
            }
        };

        float acc[2][8][4];
#pragma unroll
        for (int mi = 0; mi < 2; mi++)
#pragma unroll
            for (int ni = 0; ni < 8; ni++)
#pragma unroll
                for (int q = 0; q < 4; q++) acc[mi][ni][q] = 0.f;

        load_tile(0, 0); CP_COMMIT();
        load_tile(1, 1); CP_COMMIT();
        load_tile(2, 2); CP_COMMIT();

        for (int i = 0; i < KT; i++) {
            CP_WAIT2();
            __syncthreads();
            const int s = i % 3;
            const uint32_t* Aw = dsw + (size_t)s * ST_W;
            const uint32_t* Bs = Aw + A_W;
#pragma unroll
            for (int ks = 0; ks < 2; ks++) {         // two k16 steps per BK32
                uint32_t af[2][4];
#pragma unroll
                for (int mi = 0; mi < 2; mi++) {
                    const int r = wm + mi * 16 + g;
                    if (FIRST) {
                        // fp32 pairs -> bf16x2 (word base r*36 + ks*16 + 2t, even)
                        const float2* A2 = (const float2*)Aw;
                        af[mi][0] = cvtpack(A2[r * 18 + ks * 8 + t]);
                        af[mi][1] = cvtpack(A2[(r + 8) * 18 + ks * 8 + t]);
                        af[mi][2] = cvtpack(A2[r * 18 + ks * 8 + 4 + t]);
                        af[mi][3] = cvtpack(A2[(r + 8) * 18 + ks * 8 + 4 + t]);
                    } else {
                        // g_hb words are already k-pair packed bf16x2
                        af[mi][0] = Aw[r * 20 + ks * 8 + t];
                        af[mi][1] = Aw[(r + 8) * 20 + ks * 8 + t];
                        af[mi][2] = Aw[r * 20 + ks * 8 + 4 + t];
                        af[mi][3] = Aw[(r + 8) * 20 + ks * 8 + 4 + t];
                    }
                }
                const int k0 = ks * 16 + 2 * t;
#pragma unroll
                for (int ni = 0; ni < 8; ni++) {
                    const int cw = (wn >> 1) + ni * 4 + (g >> 1);
                    uint32_t b0 = prmt(Bs[k0 * 68 + cw],
                                       Bs[(k0 + 1) * 68 + cw], psel);
                    uint32_t b1 = prmt(Bs[(k0 + 8) * 68 + cw],
                                       Bs[(k0 + 9) * 68 + cw], psel);
                    MMA_BF16(acc[0][ni], af[0][0], af[0][1], af[0][2], af[0][3], b0, b1);
                    MMA_BF16(acc[1][ni], af[1][0], af[1][1], af[1][2], af[1][3], b0, b1);
                }
            }
            __syncthreads();
            if (i + 3 < KT) load_tile(i + 3, s);
            CP_COMMIT();
        }

        // -------- epilogue (unchanged; C map identical for k16) --------
#pragma unroll
        for (int mi = 0; mi < 2; mi++) {
            const int row0 = m0 + wm + mi * 16 + g;
            const int row1 = row0 + 8;
#pragma unroll
            for (int ni = 0; ni < 8; ni++) {
                const int col = n0 + wn + ni * 8 + 2 * t;
                const float2 bb = *(const float2*)(bias + e * N + col);
                float v0 = acc[mi][ni][0] + bb.x;
                float v1 = acc[mi][ni][1] + bb.y;
                float v2 = acc[mi][ni][2] + bb.x;
                float v3 = acc[mi][ni][3] + bb.y;
                if (FIRST) {
                    v0 = gelu(v0); v1 = gelu(v1); v2 = gelu(v2); v3 = gelu(v3);
                    uint32_t p0, p1;  // lo = even col, hi = odd col
                    asm("cvt.rn.bf16x2.f32 %0, %1, %2;" : "=r"(p0) : "f"(v1), "f"(v0));
                    asm("cvt.rn.bf16x2.f32 %0, %1, %2;" : "=r"(p1) : "f"(v3), "f"(v2));
                    if (row0 < mEnd)
                        *(uint32_t*)(g_hb + (size_t)row0 * HID + col) = p0;
                    if (row1 < mEnd)
                        *(uint32_t*)(g_hb + (size_t)row1 * HID + col) = p1;
                } else {
                    if (row0 < mEnd) {
                        float2 o = {v0, v1};
                        *(float2*)(g_o + (size_t)row0 * DIM + col) = o;
                    }
                    if (row1 < mEnd) {
                        float2 o = {v2, v3};
                        *(float2*)(g_o + (size_t)row1 * DIM + col) = o;
                    }
                }
            }
        }
        __syncthreads();
    }
}

// ---------------- combine: y = x + w0*o[s0] + w1*o[s1] ----------------------
__global__ void k_combine(const float* __restrict__ x, float* __restrict__ y,
                          int T) {
    int i = blockIdx.x * blockDim.x + threadIdx.x;
    int total = T * (DIM / 4);
    if (i >= total) return;
    int t = i / (DIM / 4);
    int d = (i - t * (DIM / 4)) * 4;
    float w0 = g_tw[2 * t], w1 = g_tw[2 * t + 1];
    int s0 = g_slot_of[2 * t], s1 = g_slot_of[2 * t + 1];
    float4 xv = *(const float4*)(x + (size_t)t * DIM + d);
    float4 o0 = *(const float4*)(g_o + (size_t)s0 * DIM + d);
    float4 o1 = *(const float4*)(g_o + (size_t)s1 * DIM + d);
    float4 r;
    r.x = xv.x + w0 * o0.x + w1 * o1.x;
    r.y = xv.y + w0 * o0.y + w1 * o1.y;
    r.z = xv.z + w0 * o0.z + w1 * o1.z;
    r.w = xv.w + w0 * o0.w + w1 * o1.w;
    *(float4*)(y + (size_t)t * DIM + d) = r;
}

// ---------------- launch -----------------------------------------------------
#define SMEM1 (3 * (128 * 36 + 32 * 68) * 4)   // 81408
#define SMEM2 (3 * (128 * 20 + 32 * 68) * 4)   // 56832

extern "C" void kernel_launch(void* const* d_in, const int* in_sizes, int n_in,
                              void* d_out, int out_size) {
    const float* x  = (const float*)d_in[0];
    const float* Wr = (const float*)d_in[1];
    const float* br = (const float*)d_in[2];
    const float* W1 = (const float*)d_in[3];
    const float* b1 = (const float*)d_in[4];
    const float* W2 = (const float*)d_in[5];
    const float* b2 = (const float*)d_in[6];
    float* y = (float*)d_out;
    const int T = in_sizes[0] / DIM;

    cudaFuncSetAttribute(k_gemm<true>,  cudaFuncAttributeMaxDynamicSharedMemorySize, SMEM1);
    cudaFuncSetAttribute(k_gemm<false>, cudaFuncAttributeMaxDynamicSharedMemorySize, SMEM2);

    __nv_bfloat16* w1b; cudaGetSymbolAddress((void**)&w1b, g_w1b);
    __nv_bfloat16* w2b; cudaGetSymbolAddress((void**)&w2b, g_w2b);

    k_init<<<1, 32>>>();
    {
        int n4 = NE * DIM * HID / 4;
        k_cvt<<<(n4 + 255) / 256, 256>>>(W1, w1b, n4);
        k_cvt<<<(n4 + 255) / 256, 256>>>(W2, w2b, n4);
    }
    k_router<<<(T + 31) / 32, 256>>>(x, Wr, br, T);
    k_scan<<<1, 32>>>();
    k_scatter<<<(2 * T + 255) / 256, 256>>>(T);

    k_gemm<true ><<<296, 256, SMEM1>>>(x, w1b, b1);
    k_gemm<false><<<296, 256, SMEM2>>>(nullptr, w2b, b2);
    k_combine<<<(T * (DIM / 4) + 255) / 256, 256>>>(x, y, T);
}

// round 10
// speedup vs baseline: 1.5035x; 1.0433x over previous
#include <cuda_runtime.h>
#include <cuda_bf16.h>
#include <math.h>
#include <stdint.h>

#define NE 16
#define DIM 512
#define HID 1024
#define MAXT 8192
#define MAXSLOTS (MAXT * 2)

// ---------------- scratch (device globals; no allocation allowed) ----------
__device__ int   g_cnt[NE];
__device__ int   g_cursor[NE];
__device__ int   g_off[NE + 1];
__device__ int   g_tp[NE + 1];
__device__ int   g_tidx[MAXSLOTS];
__device__ float g_tw[MAXSLOTS];
__device__ int   g_slot_token[MAXSLOTS];
__device__ int   g_slot_of[MAXSLOTS];
__device__ __nv_bfloat16 g_hb[(size_t)MAXSLOTS * HID];   // gelu(h) bf16, 32 MB
__device__ float         g_o [(size_t)MAXSLOTS * DIM];   // expert out fp32, 32 MB
__device__ __nv_bfloat16 g_w1b[(size_t)NE * DIM * HID];  // W1 bf16, SAME [E][K][N]
__device__ __nv_bfloat16 g_w2b[(size_t)NE * HID * DIM];  // W2 bf16, SAME [E][K][N]

// ---------------- PTX helpers ------------------------------------------------
__device__ __forceinline__ uint32_t smem_u32(const void* p) {
    uint32_t a;
    asm("{ .reg .u64 t; cvta.to.shared.u64 t, %1; cvt.u32.u64 %0, t; }"
        : "=r"(a) : "l"(p));
    return a;
}

#define CP_ASYNC16(dst, src) \
    asm volatile("cp.async.cg.shared.global [%0], [%1], 16;" \
                 :: "r"(dst), "l"(src) : "memory")
#define CP_COMMIT() asm volatile("cp.async.commit_group;" ::: "memory")
#define CP_WAIT2()  asm volatile("cp.async.wait_group 2;"  ::: "memory")

#define MMA_BF16(c, a0, a1, a2, a3, b0, b1) \
    asm volatile("mma.sync.aligned.m16n8k16.row.col.f32.bf16.bf16.f32 " \
                 "{%0,%1,%2,%3}, {%4,%5,%6,%7}, {%8,%9}, {%0,%1,%2,%3};" \
                 : "+f"((c)[0]), "+f"((c)[1]), "+f"((c)[2]), "+f"((c)[3]) \
                 : "r"(a0), "r"(a1), "r"(a2), "r"(a3), "r"(b0), "r"(b1))

// pack two fp32 -> bf16x2 {lo = v.x (even k), hi = v.y (odd k)}
__device__ __forceinline__ uint32_t cvtpack(float2 v) {
    uint32_t d;
    asm("cvt.rn.bf16x2.f32 %0, %1, %2;" : "=r"(d) : "f"(v.y), "f"(v.x));
    return d;
}

__device__ __forceinline__ uint32_t prmt(uint32_t a, uint32_t b, uint32_t sel) {
    uint32_t d;
    asm("prmt.b32 %0, %1, %2, %3;" : "=r"(d) : "r"(a), "r"(b), "r"(sel));
    return d;
}

// ---------------- small kernels ---------------------------------------------
__global__ void k_init() { if (threadIdx.x < NE) g_cnt[threadIdx.x] = 0; }

// router v3: Wr staged in smem once per block; 4 threads per token (d mod 4),
// shfl-reduce, exact fp32 top-2 (same code path as verified rounds 1-9).
// smem layout: wrs[d*17 + e] -> q-lanes hit 4 distinct banks, token lanes
// broadcast => conflict-free scalar LDS.
__global__ void __launch_bounds__(256)
k_router(const float* __restrict__ x, const float* __restrict__ Wr,
         const float* __restrict__ br, int T) {
    __shared__ float wrs[DIM * 17];
    for (int i = threadIdx.x; i < DIM * NE; i += 256) {
        int d = i >> 4, e = i & 15;
        wrs[d * 17 + e] = Wr[i];
    }
    __syncthreads();

    const int lane = threadIdx.x & 31;
    const int w    = threadIdx.x >> 5;
    const int q    = lane & 3;
    const int tok  = blockIdx.x * 64 + w * 8 + (lane >> 2);
    const int tokc = min(tok, T - 1);

    float acc[NE];
#pragma unroll
    for (int e = 0; e < NE; e++) acc[e] = 0.f;

    const float* xr = x + (size_t)tokc * DIM;
#pragma unroll 4
    for (int i = 0; i < DIM / 4; i++) {
        const int d = i * 4 + q;
        const float xs = xr[d];
        const float* wrow = wrs + d * 17;
#pragma unroll
        for (int e = 0; e < NE; e++) acc[e] = fmaf(xs, wrow[e], acc[e]);
    }
#pragma unroll
    for (int off = 1; off <= 2; off <<= 1)
#pragma unroll
        for (int e = 0; e < NE; e++)
            acc[e] += __shfl_xor_sync(0xffffffffu, acc[e], off);

    if (q == 0 && tok < T) {
        float l[NE];
#pragma unroll
        for (int e = 0; e < NE; e++) l[e] = acc[e] + br[e];
        int b0 = 0; float l0 = l[0];
#pragma unroll
        for (int e = 1; e < NE; e++) if (l[e] > l0) { l0 = l[e]; b0 = e; }
        int b1 = -1; float l1 = -3.0e38f;
#pragma unroll
        for (int e = 0; e < NE; e++)
            if (e != b0 && l[e] > l1) { l1 = l[e]; b1 = e; }
        float w0 = 1.f / (1.f + expf(l1 - l0));
        g_tidx[2 * tok] = b0; g_tidx[2 * tok + 1] = b1;
        g_tw[2 * tok] = w0;   g_tw[2 * tok + 1] = 1.f - w0;
        atomicAdd(&g_cnt[b0], 1);
        atomicAdd(&g_cnt[b1], 1);
    }
}

__global__ void k_scan() {
    if (threadIdx.x == 0) {
        g_off[0] = 0; g_tp[0] = 0;
        for (int e = 0; e < NE; e++) {
            int c = g_cnt[e];
            g_off[e + 1] = g_off[e] + c;
            g_cursor[e] = g_off[e];
            g_tp[e + 1] = g_tp[e] + (c + 127) / 128;
        }
    }
}

__global__ void k_scatter(int T) {
    int i = blockIdx.x * blockDim.x + threadIdx.x;
    if (i >= 2 * T) return;
    int e = g_tidx[i];
    int pos = atomicAdd(&g_cursor[e], 1);
    g_slot_token[pos] = i >> 1;
    g_slot_of[i] = pos;
}

// elementwise fp32 -> bf16, SAME layout (no transpose)
__global__ void k_cvt(const float* __restrict__ W,
                      __nv_bfloat16* __restrict__ Wb, int n4) {
    int i = blockIdx.x * blockDim.x + threadIdx.x;
    if (i >= n4) return;
    float4 v = *(const float4*)(W + (size_t)i * 4);
    __nv_bfloat162 a = __floats2bfloat162_rn(v.x, v.y);
    __nv_bfloat162 b = __floats2bfloat162_rn(v.z, v.w);
    uint2 o;
    o.x = *(uint32_t*)&a;
    o.y = *(uint32_t*)&b;
    *(uint2*)(Wb + (size_t)i * 4) = o;
}

__device__ __forceinline__ float gelu(float v) {
    return 0.5f * v * (1.f + erff(v * 0.70710678118654752f));
}

// ---------------- grouped GEMM: bf16 mma m16n8k16, 3-stage cp.async ---------
// (byte-identical to round 9 -- hardware verified at 295us)
template <bool FIRST>
__global__ void __launch_bounds__(256, 2)
k_gemm(const float* __restrict__ Xf,
       const __nv_bfloat16* __restrict__ Bw,
       const float* __restrict__ bias) {
    constexpr int N   = FIRST ? HID : DIM;
    constexpr int K   = FIRST ? DIM : HID;
    constexpr int KT  = K / 32;
    constexpr int NT  = N / 128;
    constexpr int AW  = FIRST ? 36 : 20;
    constexpr int A_W = 128 * AW;
    constexpr int B_W = 32 * 68;
    constexpr int ST_W = A_W + B_W;
    constexpr uint32_t ST_B = ST_W * 4;

    extern __shared__ uint32_t dsw[];
    const uint32_t sb = smem_u32(dsw);

    const int tid  = threadIdx.x;
    const int lane = tid & 31;
    const int wid  = tid >> 5;
    const int wm   = (wid & 3) * 32;
    const int wn   = (wid >> 2) * 64;
    const int g    = lane >> 2;
    const int t    = lane & 3;
    const uint32_t psel = (g & 1) ? 0x7632u : 0x5410u;

    const int total = g_tp[NE] * NT;

    for (int work = blockIdx.x; work < total; work += gridDim.x) {
        const int mt = work / NT;
        const int nt = work - mt * NT;
        int e = 0;
        while (g_tp[e + 1] <= mt) e++;
        const int m0   = g_off[e] + (mt - g_tp[e]) * 128;
        const int mEnd = g_off[e + 1];
        const int n0   = nt * 128;
        const __nv_bfloat16* Be = Bw + (size_t)e * K * N + n0;

        auto load_tile = [&](int kt, int s) {
            const uint32_t ab = sb + (uint32_t)s * ST_B;
            const uint32_t bb = ab + A_W * 4;
            if (FIRST) {
#pragma unroll
                for (int j = 0; j < 4; j++) {
                    int idx = tid + j * 256;
                    int row = idx >> 3, c = idx & 7;
                    int rg = min(m0 + row, mEnd - 1);
                    const float* src = Xf + (size_t)g_slot_token[rg] * K
                                          + kt * 32 + c * 4;
                    CP_ASYNC16(ab + (uint32_t)(row * 144 + c * 16), src);
                }
            } else {
#pragma unroll
                for (int j = 0; j < 2; j++) {
                    int idx = tid + j * 256;
                    int row = idx >> 2, c = idx & 3;
                    int rg = min(m0 + row, mEnd - 1);
                    const char* src = (const char*)g_hb
                        + ((size_t)rg * HID + kt * 32) * 2 + c * 16;
                    CP_ASYNC16(ab + (uint32_t)(row * 80 + c * 16), src);
                }
            }
#pragma unroll
            for (int j = 0; j < 2; j++) {
                int idx = tid + j * 256;
                int row = idx >> 4, c = idx & 15;
                const char* src = (const char*)Be
                    + ((size_t)(kt * 32 + row) * N) * 2 + c * 16;
                CP_ASYNC16(bb + (uint32_t)(row * 272 + c * 16), src);
            }
        };

        float acc[2][8][4];
#pragma unroll
        for (int mi = 0; mi < 2; mi++)
#pragma unroll
            for (int ni = 0; ni < 8; ni++)
#pragma unroll
                for (int q = 0; q < 4; q++) acc[mi][ni][q] = 0.f;

        load_tile(0, 0); CP_COMMIT();
        load_tile(1, 1); CP_COMMIT();
        load_tile(2, 2); CP_COMMIT();

        for (int i = 0; i < KT; i++) {
            CP_WAIT2();
            __syncthreads();
            const int s = i % 3;
            const uint32_t* Aw = dsw + (size_t)s * ST_W;
            const uint32_t* Bs = Aw + A_W;
#pragma unroll
            for (int ks = 0; ks < 2; ks++) {
                uint32_t af[2][4];
#pragma unroll
                for (int mi = 0; mi < 2; mi++) {
                    const int r = wm + mi * 16 + g;
                    if (FIRST) {
                        const float2* A2 = (const float2*)Aw;
                        af[mi][0] = cvtpack(A2[r * 18 + ks * 8 + t]);
                        af[mi][1] = cvtpack(A2[(r + 8) * 18 + ks * 8 + t]);
                        af[mi][2] = cvtpack(A2[r * 18 + ks * 8 + 4 + t]);
                        af[mi][3] = cvtpack(A2[(r + 8) * 18 + ks * 8 + 4 + t]);
                    } else {
                        af[mi][0] = Aw[r * 20 + ks * 8 + t];
                        af[mi][1] = Aw[(r + 8) * 20 + ks * 8 + t];
                        af[mi][2] = Aw[r * 20 + ks * 8 + 4 + t];
                        af[mi][3] = Aw[(r + 8) * 20 + ks * 8 + 4 + t];
                    }
                }
                const int k0 = ks * 16 + 2 * t;
#pragma unroll
                for (int ni = 0; ni < 8; ni++) {
                    const int cw = (wn >> 1) + ni * 4 + (g >> 1);
                    uint32_t b0 = prmt(Bs[k0 * 68 + cw],
                                       Bs[(k0 + 1) * 68 + cw], psel);
                    uint32_t b1 = prmt(Bs[(k0 + 8) * 68 + cw],
                                       Bs[(k0 + 9) * 68 + cw], psel);
                    MMA_BF16(acc[0][ni], af[0][0], af[0][1], af[0][2], af[0][3], b0, b1);
                    MMA_BF16(acc[1][ni], af[1][0], af[1][1], af[1][2], af[1][3], b0, b1);
                }
            }
            __syncthreads();
            if (i + 3 < KT) load_tile(i + 3, s);
            CP_COMMIT();
        }

#pragma unroll
        for (int mi = 0; mi < 2; mi++) {
            const int row0 = m0 + wm + mi * 16 + g;
            const int row1 = row0 + 8;
#pragma unroll
            for (int ni = 0; ni < 8; ni++) {
                const int col = n0 + wn + ni * 8 + 2 * t;
                const float2 bb = *(const float2*)(bias + e * N + col);
                float v0 = acc[mi][ni][0] + bb.x;
                float v1 = acc[mi][ni][1] + bb.y;
                float v2 = acc[mi][ni][2] + bb.x;
                float v3 = acc[mi][ni][3] + bb.y;
                if (FIRST) {
                    v0 = gelu(v0); v1 = gelu(v1); v2 = gelu(v2); v3 = gelu(v3);
                    uint32_t p0, p1;
                    asm("cvt.rn.bf16x2.f32 %0, %1, %2;" : "=r"(p0) : "f"(v1), "f"(v0));
                    asm("cvt.rn.bf16x2.f32 %0, %1, %2;" : "=r"(p1) : "f"(v3), "f"(v2));
                    if (row0 < mEnd)
                        *(uint32_t*)(g_hb + (size_t)row0 * HID + col) = p0;
                    if (row1 < mEnd)
                        *(uint32_t*)(g_hb + (size_t)row1 * HID + col) = p1;
                } else {
                    if (row0 < mEnd) {
                        float2 o = {v0, v1};
                        *(float2*)(g_o + (size_t)row0 * DIM + col) = o;
                    }
                    if (row1 < mEnd) {
                        float2 o = {v2, v3};
                        *(float2*)(g_o + (size_t)row1 * DIM + col) = o;
                    }
                }
            }
        }
        __syncthreads();
    }
}

// ---------------- combine: y = x + w0*o[s0] + w1*o[s1] ----------------------
__global__ void k_combine(const float* __restrict__ x, float* __restrict__ y,
                          int T) {
    int i = blockIdx.x * blockDim.x + threadIdx.x;
    int total = T * (DIM / 4);
    if (i >= total) return;
    int t = i / (DIM / 4);
    int d = (i - t * (DIM / 4)) * 4;
    float w0 = g_tw[2 * t], w1 = g_tw[2 * t + 1];
    int s0 = g_slot_of[2 * t], s1 = g_slot_of[2 * t + 1];
    float4 xv = *(const float4*)(x + (size_t)t * DIM + d);
    float4 o0 = *(const float4*)(g_o + (size_t)s0 * DIM + d);
    float4 o1 = *(const float4*)(g_o + (size_t)s1 * DIM + d);
    float4 r;
    r.x = xv.x + w0 * o0.x + w1 * o1.x;
    r.y = xv.y + w0 * o0.y + w1 * o1.y;
    r.z = xv.z + w0 * o0.z + w1 * o1.z;
    r.w = xv.w + w0 * o0.w + w1 * o1.w;
    *(float4*)(y + (size_t)t * DIM + d) = r;
}

// ---------------- launch -----------------------------------------------------
#define SMEM1 (3 * (128 * 36 + 32 * 68) * 4)   // 81408
#define SMEM2 (3 * (128 * 20 + 32 * 68) * 4)   // 56832

extern "C" void kernel_launch(void* const* d_in, const int* in_sizes, int n_in,
                              void* d_out, int out_size) {
    const float* x  = (const float*)d_in[0];
    const float* Wr = (const float*)d_in[1];
    const float* br = (const float*)d_in[2];
    const float* W1 = (const float*)d_in[3];
    const float* b1 = (const float*)d_in[4];
    const float* W2 = (const float*)d_in[5];
    const float* b2 = (const float*)d_in[6];
    float* y = (float*)d_out;
    const int T = in_sizes[0] / DIM;

    cudaFuncSetAttribute(k_gemm<true>,  cudaFuncAttributeMaxDynamicSharedMemorySize, SMEM1);
    cudaFuncSetAttribute(k_gemm<false>, cudaFuncAttributeMaxDynamicSharedMemorySize, SMEM2);

    __nv_bfloat16* w1b; cudaGetSymbolAddress((void**)&w1b, g_w1b);
    __nv_bfloat16* w2b; cudaGetSymbolAddress((void**)&w2b, g_w2b);

    k_init<<<1, 32>>>();
    {
        int n4 = NE * DIM * HID / 4;
        k_cvt<<<(n4 + 255) / 256, 256>>>(W1, w1b, n4);
        k_cvt<<<(n4 + 255) / 256, 256>>>(W2, w2b, n4);
    }
    k_router<<<(T + 63) / 64, 256>>>(x, Wr, br, T);
    k_scan<<<1, 32>>>();
    k_scatter<<<(2 * T + 255) / 256, 256>>>(T);

    k_gemm<true ><<<296, 256, SMEM1>>>(x, w1b, b1);
    k_gemm<false><<<296, 256, SMEM2>>>(nullptr, w2b, b2);
    k_combine<<<(T * (DIM / 4) + 255) / 256, 256>>>(x, y, T);
}

// round 11
// speedup vs baseline: 1.7319x; 1.1519x over previous
#include <cuda_runtime.h>
#include <cuda_bf16.h>
#include <math.h>
#include <stdint.h>

#define NE 16
#define DIM 512
#define HID 1024
#define MAXT 8192
#define MAXSLOTS (MAXT * 2)

// ---------------- scratch (device globals; no allocation allowed) ----------
__device__ int   g_cnt[NE];
__device__ int   g_cursor[NE];
__device__ int   g_off[NE + 1];
__device__ int   g_tp[NE + 1];
__device__ int   g_tidx[MAXSLOTS];
__device__ float g_tw[MAXSLOTS];
__device__ int   g_slot_token[MAXSLOTS];
__device__ int   g_slot_of[MAXSLOTS];
__device__ __nv_bfloat16 g_xb[(size_t)MAXT * DIM];       // x bf16 (same layout)
__device__ __nv_bfloat16 g_hb[(size_t)MAXSLOTS * HID];   // gelu(h) bf16
__device__ float         g_o [(size_t)MAXSLOTS * DIM];   // expert out fp32
__device__ __nv_bfloat16 g_w1b[(size_t)NE * DIM * HID];  // W1 bf16, SAME [E][K][N]
__device__ __nv_bfloat16 g_w2b[(size_t)NE * HID * DIM];  // W2 bf16, SAME [E][K][N]

// ---------------- PTX helpers ------------------------------------------------
__device__ __forceinline__ uint32_t smem_u32(const void* p) {
    uint32_t a;
    asm("{ .reg .u64 t; cvta.to.shared.u64 t, %1; cvt.u32.u64 %0, t; }"
        : "=r"(a) : "l"(p));
    return a;
}

#define CP_ASYNC16(dst, src) \
    asm volatile("cp.async.cg.shared.global [%0], [%1], 16;" \
                 :: "r"(dst), "l"(src) : "memory")
#define CP_COMMIT() asm volatile("cp.async.commit_group;" ::: "memory")
#define CP_WAIT2()  asm volatile("cp.async.wait_group 2;"  ::: "memory")

#define MMA_BF16(c, a0, a1, a2, a3, b0, b1) \
    asm volatile("mma.sync.aligned.m16n8k16.row.col.f32.bf16.bf16.f32 " \
                 "{%0,%1,%2,%3}, {%4,%5,%6,%7}, {%8,%9}, {%0,%1,%2,%3};" \
                 : "+f"((c)[0]), "+f"((c)[1]), "+f"((c)[2]), "+f"((c)[3]) \
                 : "r"(a0), "r"(a1), "r"(a2), "r"(a3), "r"(b0), "r"(b1))

__device__ __forceinline__ uint32_t prmt(uint32_t a, uint32_t b, uint32_t sel) {
    uint32_t d;
    asm("prmt.b32 %0, %1, %2, %3;" : "=r"(d) : "r"(a), "r"(b), "r"(sel));
    return d;
}

// ---------------- small kernels ---------------------------------------------
__global__ void k_init() { if (threadIdx.x < NE) g_cnt[threadIdx.x] = 0; }

// router v4: Wr in smem; 32 tokens/block, 8 threads per token (d mod 8).
// banks: 17*q mod 32 = {0,17,2,19,4,21,6,23} distinct; token lanes broadcast.
__global__ void __launch_bounds__(256)
k_router(const float* __restrict__ x, const float* __restrict__ Wr,
         const float* __restrict__ br, int T) {
    __shared__ float wrs[DIM * 17];
    for (int i = threadIdx.x; i < DIM * NE; i += 256) {
        int d = i >> 4, e = i & 15;
        wrs[d * 17 + e] = Wr[i];
    }
    __syncthreads();

    const int lane = threadIdx.x & 31;
    const int w    = threadIdx.x >> 5;
    const int q    = lane & 7;
    const int tok  = blockIdx.x * 32 + w * 4 + (lane >> 3);
    const int tokc = min(tok, T - 1);

    float acc[NE];
#pragma unroll
    for (int e = 0; e < NE; e++) acc[e] = 0.f;

    const float* xr = x + (size_t)tokc * DIM;
#pragma unroll 4
    for (int i = 0; i < DIM / 8; i++) {
        const int d = i * 8 + q;
        const float xs = xr[d];
        const float* wrow = wrs + d * 17;
#pragma unroll
        for (int e = 0; e < NE; e++) acc[e] = fmaf(xs, wrow[e], acc[e]);
    }
#pragma unroll
    for (int off = 1; off <= 4; off <<= 1)
#pragma unroll
        for (int e = 0; e < NE; e++)
            acc[e] += __shfl_xor_sync(0xffffffffu, acc[e], off);

    if (q == 0 && tok < T) {
        float l[NE];
#pragma unroll
        for (int e = 0; e < NE; e++) l[e] = acc[e] + br[e];
        int b0 = 0; float l0 = l[0];
#pragma unroll
        for (int e = 1; e < NE; e++) if (l[e] > l0) { l0 = l[e]; b0 = e; }
        int b1 = -1; float l1 = -3.0e38f;
#pragma unroll
        for (int e = 0; e < NE; e++)
            if (e != b0 && l[e] > l1) { l1 = l[e]; b1 = e; }
        float w0 = 1.f / (1.f + expf(l1 - l0));
        g_tidx[2 * tok] = b0; g_tidx[2 * tok + 1] = b1;
        g_tw[2 * tok] = w0;   g_tw[2 * tok + 1] = 1.f - w0;
        atomicAdd(&g_cnt[b0], 1);
        atomicAdd(&g_cnt[b1], 1);
    }
}

__global__ void k_scan() {
    if (threadIdx.x == 0) {
        g_off[0] = 0; g_tp[0] = 0;
        for (int e = 0; e < NE; e++) {
            int c = g_cnt[e];
            g_off[e + 1] = g_off[e] + c;
            g_cursor[e] = g_off[e];
            g_tp[e + 1] = g_tp[e] + (c + 127) / 128;
        }
    }
}

__global__ void k_scatter(int T) {
    int i = blockIdx.x * blockDim.x + threadIdx.x;
    if (i >= 2 * T) return;
    int e = g_tidx[i];
    int pos = atomicAdd(&g_cursor[e], 1);
    g_slot_token[pos] = i >> 1;
    g_slot_of[i] = pos;
}

// elementwise fp32 -> bf16, SAME layout (verified round 8-10)
__global__ void k_cvt(const float* __restrict__ W,
                      __nv_bfloat16* __restrict__ Wb, int n4) {
    int i = blockIdx.x * blockDim.x + threadIdx.x;
    if (i >= n4) return;
    float4 v = *(const float4*)(W + (size_t)i * 4);
    __nv_bfloat162 a = __floats2bfloat162_rn(v.x, v.y);
    __nv_bfloat162 b = __floats2bfloat162_rn(v.z, v.w);
    uint2 o;
    o.x = *(uint32_t*)&a;
    o.y = *(uint32_t*)&b;
    *(uint2*)(Wb + (size_t)i * 4) = o;
}

__device__ __forceinline__ float gelu(float v) {
    return 0.5f * v * (1.f + erff(v * 0.70710678118654752f));
}

// ---------------- grouped GEMM: bf16 m16n8k16, 4-stage, 1 sync/iter ---------
// FIRST: g_hb = bf16(gelu(gather(g_xb) @ W1b[e] + b1[e])),  N=HID, K=DIM
// else : g_o  = g_hb @ W2b[e] + b2[e],                      N=DIM, K=HID
// A stage: bf16, 128 x (16+4) words, stride 20 (80B rows; verified round 9/10)
// B stage: bf16,  32 x (64+4) words, stride 68 (272B rows; verified)
#define A_W  (128 * 20)
#define B_W  (32 * 68)
#define ST_W (A_W + B_W)            // 4736 words
#define ST_B ((uint32_t)(ST_W * 4)) // 18944 bytes
#define GEMM_SMEM (4 * ST_W * 4)    // 75776 bytes

template <bool FIRST>
__global__ void __launch_bounds__(256, 2)
k_gemm(const __nv_bfloat16* __restrict__ Ab,
       const __nv_bfloat16* __restrict__ Bw,
       const float* __restrict__ bias) {
    constexpr int N   = FIRST ? HID : DIM;
    constexpr int K   = FIRST ? DIM : HID;
    constexpr int KT  = K / 32;
    constexpr int NT  = N / 128;

    extern __shared__ uint32_t dsw[];
    const uint32_t sb = smem_u32(dsw);

    const int tid  = threadIdx.x;
    const int lane = tid & 31;
    const int wid  = tid >> 5;
    const int wm   = (wid & 3) * 32;
    const int wn   = (wid >> 2) * 64;
    const int g    = lane >> 2;
    const int t    = lane & 3;
    const uint32_t psel = (g & 1) ? 0x7632u : 0x5410u;

    const int total = g_tp[NE] * NT;

    for (int work = blockIdx.x; work < total; work += gridDim.x) {
        const int mt = work / NT;
        const int nt = work - mt * NT;
        int e = 0;
        while (g_tp[e + 1] <= mt) e++;
        const int m0   = g_off[e] + (mt - g_tp[e]) * 128;
        const int mEnd = g_off[e + 1];
        const int n0   = nt * 128;
        const __nv_bfloat16* Be = Bw + (size_t)e * K * N + n0;

        // loader: A bf16 (stride 80B, verified); FIRST gathers via slot_token
        auto load_tile = [&](int kt, int s) {
            const uint32_t ab = sb + (uint32_t)s * ST_B;
            const uint32_t bb = ab + A_W * 4;
#pragma unroll
            for (int j = 0; j < 2; j++) {
                int idx = tid + j * 256;
                int row = idx >> 2, c = idx & 3;
                int rg = min(m0 + row, mEnd - 1);
                const char* src;
                if (FIRST)
                    src = (const char*)g_xb
                        + ((size_t)g_slot_token[rg] * DIM + kt * 32) * 2 + c * 16;
                else
                    src = (const char*)g_hb
                        + ((size_t)rg * HID + kt * 32) * 2 + c * 16;
                CP_ASYNC16(ab + (uint32_t)(row * 80 + c * 16), src);
            }
#pragma unroll
            for (int j = 0; j < 2; j++) {
                int idx = tid + j * 256;
                int row = idx >> 4, c = idx & 15;
                const char* src = (const char*)Be
                    + ((size_t)(kt * 32 + row) * N) * 2 + c * 16;
                CP_ASYNC16(bb + (uint32_t)(row * 272 + c * 16), src);
            }
        };

        float acc[2][8][4];
#pragma unroll
        for (int mi = 0; mi < 2; mi++)
#pragma unroll
            for (int ni = 0; ni < 8; ni++)
#pragma unroll
                for (int q = 0; q < 4; q++) acc[mi][ni][q] = 0.f;

        load_tile(0, 0); CP_COMMIT();
        load_tile(1, 1); CP_COMMIT();
        load_tile(2, 2); CP_COMMIT();

        for (int i = 0; i < KT; i++) {
            CP_WAIT2();
            __syncthreads();   // stage i%4 ready; also orders iter i-1 reads
                               // before this iter's write of stage (i-1)%4
            const int s = i & 3;
            const uint32_t* Aw = dsw + (size_t)s * ST_W;
            const uint32_t* Bs = Aw + A_W;
#pragma unroll
            for (int ks = 0; ks < 2; ks++) {
                uint32_t af[2][4];
#pragma unroll
                for (int mi = 0; mi < 2; mi++) {
                    const int r = wm + mi * 16 + g;
                    af[mi][0] = Aw[r * 20 + ks * 8 + t];
                    af[mi][1] = Aw[(r + 8) * 20 + ks * 8 + t];
                    af[mi][2] = Aw[r * 20 + ks * 8 + 4 + t];
                    af[mi][3] = Aw[(r + 8) * 20 + ks * 8 + 4 + t];
                }
                const int k0 = ks * 16 + 2 * t;
#pragma unroll
                for (int ni = 0; ni < 8; ni++) {
                    const int cw = (wn >> 1) + ni * 4 + (g >> 1);
                    uint32_t b0 = prmt(Bs[k0 * 68 + cw],
                                       Bs[(k0 + 1) * 68 + cw], psel);
                    uint32_t b1 = prmt(Bs[(k0 + 8) * 68 + cw],
                                       Bs[(k0 + 9) * 68 + cw], psel);
                    MMA_BF16(acc[0][ni], af[0][0], af[0][1], af[0][2], af[0][3], b0, b1);
                    MMA_BF16(acc[1][ni], af[1][0], af[1][1], af[1][2], af[1][3], b0, b1);
                }
            }
            if (i + 3 < KT) load_tile(i + 3, (i + 3) & 3);
            CP_COMMIT();
        }

        // epilogue (verified rounds 9/10)
#pragma unroll
        for (int mi = 0; mi < 2; mi++) {
            const int row0 = m0 + wm + mi * 16 + g;
            const int row1 = row0 + 8;
#pragma unroll
            for (int ni = 0; ni < 8; ni++) {
                const int col = n0 + wn + ni * 8 + 2 * t;
                const float2 bb = *(const float2*)(bias + e * N + col);
                float v0 = acc[mi][ni][0] + bb.x;
                float v1 = acc[mi][ni][1] + bb.y;
                float v2 = acc[mi][ni][2] + bb.x;
                float v3 = acc[mi][ni][3] + bb.y;
                if (FIRST) {
                    v0 = gelu(v0); v1 = gelu(v1); v2 = gelu(v2); v3 = gelu(v3);
                    uint32_t p0, p1;
                    asm("cvt.rn.bf16x2.f32 %0, %1, %2;" : "=r"(p0) : "f"(v1), "f"(v0));
                    asm("cvt.rn.bf16x2.f32 %0, %1, %2;" : "=r"(p1) : "f"(v3), "f"(v2));
                    if (row0 < mEnd)
                        *(uint32_t*)(g_hb + (size_t)row0 * HID + col) = p0;
                    if (row1 < mEnd)
                        *(uint32_t*)(g_hb + (size_t)row1 * HID + col) = p1;
                } else {
                    if (row0 < mEnd) {
                        float2 o = {v0, v1};
                        *(float2*)(g_o + (size_t)row0 * DIM + col) = o;
                    }
                    if (row1 < mEnd) {
                        float2 o = {v2, v3};
                        *(float2*)(g_o + (size_t)row1 * DIM + col) = o;
                    }
                }
            }
        }
        __syncthreads();   // cross-work hazard: next prologue rewrites stages
    }
}

// ---------------- combine: y = x + w0*o[s0] + w1*o[s1] ----------------------
__global__ void k_combine(const float* __restrict__ x, float* __restrict__ y,
                          int T) {
    int i = blockIdx.x * blockDim.x + threadIdx.x;
    int total = T * (DIM / 4);
    if (i >= total) return;
    int t = i / (DIM / 4);
    int d = (i - t * (DIM / 4)) * 4;
    float w0 = g_tw[2 * t], w1 = g_tw[2 * t + 1];
    int s0 = g_slot_of[2 * t], s1 = g_slot_of[2 * t + 1];
    float4 xv = *(const float4*)(x + (size_t)t * DIM + d);
    float4 o0 = *(const float4*)(g_o + (size_t)s0 * DIM + d);
    float4 o1 = *(const float4*)(g_o + (size_t)s1 * DIM + d);
    float4 r;
    r.x = xv.x + w0 * o0.x + w1 * o1.x;
    r.y = xv.y + w0 * o0.y + w1 * o1.y;
    r.z = xv.z + w0 * o0.z + w1 * o1.z;
    r.w = xv.w + w0 * o0.w + w1 * o1.w;
    *(float4*)(y + (size_t)t * DIM + d) = r;
}

// ---------------- launch -----------------------------------------------------
extern "C" void kernel_launch(void* const* d_in, const int* in_sizes, int n_in,
                              void* d_out, int out_size) {
    const float* x  = (const float*)d_in[0];
    const float* Wr = (const float*)d_in[1];
    const float* br = (const float*)d_in[2];
    const float* W1 = (const float*)d_in[3];
    const float* b1 = (const float*)d_in[4];
    const float* W2 = (const float*)d_in[5];
    const float* b2 = (const float*)d_in[6];
    float* y = (float*)d_out;
    const int T = in_sizes[0] / DIM;

    cudaFuncSetAttribute(k_gemm<true>,  cudaFuncAttributeMaxDynamicSharedMemorySize, GEMM_SMEM);
    cudaFuncSetAttribute(k_gemm<false>, cudaFuncAttributeMaxDynamicSharedMemorySize, GEMM_SMEM);

    __nv_bfloat16* w1b; cudaGetSymbolAddress((void**)&w1b, g_w1b);
    __nv_bfloat16* w2b; cudaGetSymbolAddress((void**)&w2b, g_w2b);
    __nv_bfloat16* xb;  cudaGetSymbolAddress((void**)&xb,  g_xb);

    k_init<<<1, 32>>>();
    {
        int n4 = NE * DIM * HID / 4;
        k_cvt<<<(n4 + 255) / 256, 256>>>(W1, w1b, n4);
        k_cvt<<<(n4 + 255) / 256, 256>>>(W2, w2b, n4);
        int x4 = T * DIM / 4;
        k_cvt<<<(x4 + 255) / 256, 256>>>(x, xb, x4);
    }
    k_router<<<(T + 31) / 32, 256>>>(x, Wr, br, T);
    k_scan<<<1, 32>>>();
    k_scatter<<<(2 * T + 255) / 256, 256>>>(T);

    k_gemm<true ><<<296, 256, GEMM_SMEM>>>(xb, w1b, b1);
    k_gemm<false><<<296, 256, GEMM_SMEM>>>(nullptr, w2b, b2);
    k_combine<<<(T * (DIM / 4) + 255) / 256, 256>>>(x, y, T);
}

// round 12
// speedup vs baseline: 1.9983x; 1.1538x over previous
#include <cuda_runtime.h>
#include <cuda_bf16.h>
#include <math.h>
#include <stdint.h>

#define NE 16
#define DIM 512
#define HID 1024
#define MAXT 8192
#define MAXSLOTS (MAXT * 2)

// ---------------- scratch (device globals; no allocation allowed) ----------
__device__ int   g_cnt[NE];
__device__ int   g_cursor[NE];
__device__ int   g_off[NE + 1];
__device__ int   g_tp[NE + 1];
__device__ int   g_tidx[MAXSLOTS];
__device__ float g_tw[MAXSLOTS];
__device__ int   g_slot_token[MAXSLOTS];
__device__ int   g_slot_of[MAXSLOTS];
__device__ __nv_bfloat16 g_xb[(size_t)MAXT * DIM];       // x bf16 (same layout)
__device__ __nv_bfloat16 g_hb[(size_t)MAXSLOTS * HID];   // gelu(h) bf16
__device__ float         g_o [(size_t)MAXSLOTS * DIM];   // expert out fp32
// weights, k-pair packed: word(kp,n) = {lo=W[2kp][n], hi=W[2kp+1][n]} bf16x2
__device__ __nv_bfloat16 g_w1p[(size_t)NE * DIM * HID];  // [E][DIM/2][HID] words
__device__ __nv_bfloat16 g_w2p[(size_t)NE * HID * DIM];  // [E][HID/2][DIM] words

// ---------------- PTX helpers ------------------------------------------------
__device__ __forceinline__ uint32_t smem_u32(const void* p) {
    uint32_t a;
    asm("{ .reg .u64 t; cvta.to.shared.u64 t, %1; cvt.u32.u64 %0, t; }"
        : "=r"(a) : "l"(p));
    return a;
}

#define CP_ASYNC16(dst, src) \
    asm volatile("cp.async.cg.shared.global [%0], [%1], 16;" \
                 :: "r"(dst), "l"(src) : "memory")
#define CP_COMMIT() asm volatile("cp.async.commit_group;" ::: "memory")
#define CP_WAIT2()  asm volatile("cp.async.wait_group 2;"  ::: "memory")

#define MMA_BF16(c, a0, a1, a2, a3, b0, b1) \
    asm volatile("mma.sync.aligned.m16n8k16.row.col.f32.bf16.bf16.f32 " \
                 "{%0,%1,%2,%3}, {%4,%5,%6,%7}, {%8,%9}, {%0,%1,%2,%3};" \
                 : "+f"((c)[0]), "+f"((c)[1]), "+f"((c)[2]), "+f"((c)[3]) \
                 : "r"(a0), "r"(a1), "r"(a2), "r"(a3), "r"(b0), "r"(b1))

// pack {lo, hi} fp32 -> bf16x2 (src0 = hi, src1 = lo; verified rounds 7-11)
__device__ __forceinline__ uint32_t packlohi(float lo, float hi) {
    uint32_t d;
    asm("cvt.rn.bf16x2.f32 %0, %1, %2;" : "=r"(d) : "f"(hi), "f"(lo));
    return d;
}

// ---------------- small kernels ---------------------------------------------
__global__ void k_init() { if (threadIdx.x < NE) g_cnt[threadIdx.x] = 0; }

// router v4 (verified round 11): Wr in smem; 32 tokens/block, 8 thr/token.
__global__ void __launch_bounds__(256)
k_router(const float* __restrict__ x, const float* __restrict__ Wr,
         const float* __restrict__ br, int T) {
    __shared__ float wrs[DIM * 17];
    for (int i = threadIdx.x; i < DIM * NE; i += 256) {
        int d = i >> 4, e = i & 15;
        wrs[d * 17 + e] = Wr[i];
    }
    __syncthreads();

    const int lane = threadIdx.x & 31;
    const int w    = threadIdx.x >> 5;
    const int q    = lane & 7;
    const int tok  = blockIdx.x * 32 + w * 4 + (lane >> 3);
    const int tokc = min(tok, T - 1);

    float acc[NE];
#pragma unroll
    for (int e = 0; e < NE; e++) acc[e] = 0.f;

    const float* xr = x + (size_t)tokc * DIM;
#pragma unroll 4
    for (int i = 0; i < DIM / 8; i++) {
        const int d = i * 8 + q;
        const float xs = xr[d];
        const float* wrow = wrs + d * 17;
#pragma unroll
        for (int e = 0; e < NE; e++) acc[e] = fmaf(xs, wrow[e], acc[e]);
    }
#pragma unroll
    for (int off = 1; off <= 4; off <<= 1)
#pragma unroll
        for (int e = 0; e < NE; e++)
            acc[e] += __shfl_xor_sync(0xffffffffu, acc[e], off);

    if (q == 0 && tok < T) {
        float l[NE];
#pragma unroll
        for (int e = 0; e < NE; e++) l[e] = acc[e] + br[e];
        int b0 = 0; float l0 = l[0];
#pragma unroll
        for (int e = 1; e < NE; e++) if (l[e] > l0) { l0 = l[e]; b0 = e; }
        int b1 = -1; float l1 = -3.0e38f;
#pragma unroll
        for (int e = 0; e < NE; e++)
            if (e != b0 && l[e] > l1) { l1 = l[e]; b1 = e; }
        float w0 = 1.f / (1.f + expf(l1 - l0));
        g_tidx[2 * tok] = b0; g_tidx[2 * tok + 1] = b1;
        g_tw[2 * tok] = w0;   g_tw[2 * tok + 1] = 1.f - w0;
        atomicAdd(&g_cnt[b0], 1);
        atomicAdd(&g_cnt[b1], 1);
    }
}

__global__ void k_scan() {
    if (threadIdx.x == 0) {
        g_off[0] = 0; g_tp[0] = 0;
        for (int e = 0; e < NE; e++) {
            int c = g_cnt[e];
            g_off[e + 1] = g_off[e] + c;
            g_cursor[e] = g_off[e];
            g_tp[e + 1] = g_tp[e] + (c + 127) / 128;
        }
    }
}

__global__ void k_scatter(int T) {
    int i = blockIdx.x * blockDim.x + threadIdx.x;
    if (i >= 2 * T) return;
    int e = g_tidx[i];
    int pos = atomicAdd(&g_cursor[e], 1);
    g_slot_token[pos] = i >> 1;
    g_slot_of[i] = pos;
}

// elementwise fp32 -> bf16, SAME layout (verified; used for x)
__global__ void k_cvt(const float* __restrict__ W,
                      __nv_bfloat16* __restrict__ Wb, int n4) {
    int i = blockIdx.x * blockDim.x + threadIdx.x;
    if (i >= n4) return;
    float4 v = *(const float4*)(W + (size_t)i * 4);
    __nv_bfloat162 a = __floats2bfloat162_rn(v.x, v.y);
    __nv_bfloat162 b = __floats2bfloat162_rn(v.z, v.w);
    uint2 o;
    o.x = *(uint32_t*)&a;
    o.y = *(uint32_t*)&b;
    *(uint2*)(Wb + (size_t)i * 4) = o;
}

// weights: [E][KK][NN] fp32 -> k-pair packed words [E][KK/2][NN] bf16x2.
// word(e,kp,n) = {lo = bf16 W[e][2kp][n], hi = bf16 W[e][2kp+1][n]}
__global__ void k_cvtpair(const float* __restrict__ W,
                          __nv_bfloat16* __restrict__ Wp, int KK, int NN) {
    int i = blockIdx.x * blockDim.x + threadIdx.x;
    int nq4 = NN / 4;
    int total = NE * (KK / 2) * nq4;
    if (i >= total) return;
    int nq = i % nq4;
    int rest = i / nq4;
    int kp = rest % (KK / 2);
    int e  = rest / (KK / 2);
    const float* base = W + ((size_t)e * KK + 2 * kp) * NN + nq * 4;
    float4 r0 = *(const float4*)base;          // k even
    float4 r1 = *(const float4*)(base + NN);   // k odd
    uint4 o;
    o.x = packlohi(r0.x, r1.x);
    o.y = packlohi(r0.y, r1.y);
    o.z = packlohi(r0.z, r1.z);
    o.w = packlohi(r0.w, r1.w);
    *(uint4*)(Wp + (((size_t)e * (KK / 2) + kp) * NN + nq * 4) * 2) = o;
}

__device__ __forceinline__ float gelu(float v) {
    return 0.5f * v * (1.f + erff(v * 0.70710678118654752f));
}

// ---------------- grouped GEMM: bf16 m16n8k16, pair-packed B ----------------
// FIRST: g_hb = bf16(gelu(gather(g_xb) @ W1 + b1)),  N=HID, K=DIM
// else : g_o  = g_hb @ W2 + b2,                      N=DIM, K=HID
// A stage: bf16, 128 x (16+4) words, stride 20 (80B rows; verified r9-11)
// B stage: pair-packed words, 16 kp-rows x (128+8) words, stride 136
//          (544B rows, 16B aligned; banks 8t+g -> 32 distinct, CF)
#define A_W  (128 * 20)
#define B_W  (16 * 136)
#define ST_W (A_W + B_W)            // 4736 words (same as round 11)
#define ST_B ((uint32_t)(ST_W * 4)) // 18944 bytes
#define GEMM_SMEM (4 * ST_W * 4)    // 75776 bytes

template <bool FIRST>
__global__ void __launch_bounds__(256, 2)
k_gemm(const __nv_bfloat16* __restrict__ Ab,
       const __nv_bfloat16* __restrict__ Bw,   // pair-packed words
       const float* __restrict__ bias) {
    constexpr int N   = FIRST ? HID : DIM;
    constexpr int K   = FIRST ? DIM : HID;
    constexpr int KT  = K / 32;
    constexpr int NT  = N / 128;

    extern __shared__ uint32_t dsw[];
    const uint32_t sb = smem_u32(dsw);

    const int tid  = threadIdx.x;
    const int lane = tid & 31;
    const int wid  = tid >> 5;
    const int wm   = (wid & 3) * 32;
    const int wn   = (wid >> 2) * 64;
    const int g    = lane >> 2;
    const int t    = lane & 3;

    const int total = g_tp[NE] * NT;

    for (int work = blockIdx.x; work < total; work += gridDim.x) {
        const int mt = work / NT;
        const int nt = work - mt * NT;
        int e = 0;
        while (g_tp[e + 1] <= mt) e++;
        const int m0   = g_off[e] + (mt - g_tp[e]) * 128;
        const int mEnd = g_off[e + 1];
        const int n0   = nt * 128;
        // word base for expert e, columns n0.. : byte address
        const char* Bep = (const char*)Bw + ((size_t)e * (K / 2) * N + n0) * 4;

        auto load_tile = [&](int kt, int s) {
            const uint32_t ab = sb + (uint32_t)s * ST_B;
            const uint32_t bb = ab + A_W * 4;
            // A: bf16, 128 rows x 4 chunks (80B rows; verified)
#pragma unroll
            for (int j = 0; j < 2; j++) {
                int idx = tid + j * 256;
                int row = idx >> 2, c = idx & 3;
                int rg = min(m0 + row, mEnd - 1);
                const char* src;
                if (FIRST)
                    src = (const char*)g_xb
                        + ((size_t)g_slot_token[rg] * DIM + kt * 32) * 2 + c * 16;
                else
                    src = (const char*)g_hb
                        + ((size_t)rg * HID + kt * 32) * 2 + c * 16;
                CP_ASYNC16(ab + (uint32_t)(row * 80 + c * 16), src);
            }
            // B: pair-packed, 16 kp-rows x 32 chunks of 16B (512B data/row)
#pragma unroll
            for (int j = 0; j < 2; j++) {
                int idx = tid + j * 256;
                int row = idx >> 5, c = idx & 31;
                const char* src = Bep + ((size_t)(kt * 16 + row) * N) * 4 + c * 16;
                CP_ASYNC16(bb + (uint32_t)(row * 544 + c * 16), src);
            }
        };

        float acc[2][8][4];
#pragma unroll
        for (int mi = 0; mi < 2; mi++)
#pragma unroll
            for (int ni = 0; ni < 8; ni++)
#pragma unroll
                for (int q = 0; q < 4; q++) acc[mi][ni][q] = 0.f;

        load_tile(0, 0); CP_COMMIT();
        load_tile(1, 1); CP_COMMIT();
        load_tile(2, 2); CP_COMMIT();

        for (int i = 0; i < KT; i++) {
            CP_WAIT2();
            __syncthreads();
            const int s = i & 3;
            const uint32_t* Aw = dsw + (size_t)s * ST_W;
            const uint32_t* Bs = Aw + A_W;
#pragma unroll
            for (int ks = 0; ks < 2; ks++) {
                uint32_t af[2][4];
#pragma unroll
                for (int mi = 0; mi < 2; mi++) {
                    const int r = wm + mi * 16 + g;
                    af[mi][0] = Aw[r * 20 + ks * 8 + t];
                    af[mi][1] = Aw[(r + 8) * 20 + ks * 8 + t];
                    af[mi][2] = Aw[r * 20 + ks * 8 + 4 + t];
                    af[mi][3] = Aw[(r + 8) * 20 + ks * 8 + 4 + t];
                }
                const int kp = ks * 8 + t;   // k-pair row (k0 = 2*kp)
#pragma unroll
                for (int ni = 0; ni < 8; ni++) {
                    const int cn = wn + ni * 8 + g;
                    uint32_t b0 = Bs[kp * 136 + cn];        // {k0, k0+1}
                    uint32_t b1 = Bs[(kp + 4) * 136 + cn];  // {k0+8, k0+9}
                    MMA_BF16(acc[0][ni], af[0][0], af[0][1], af[0][2], af[0][3], b0, b1);
                    MMA_BF16(acc[1][ni], af[1][0], af[1][1], af[1][2], af[1][3], b0, b1);
                }
            }
            if (i + 3 < KT) load_tile(i + 3, (i + 3) & 3);
            CP_COMMIT();
        }

        // epilogue (verified rounds 9-11)
#pragma unroll
        for (int mi = 0; mi < 2; mi++) {
            const int row0 = m0 + wm + mi * 16 + g;
            const int row1 = row0 + 8;
#pragma unroll
            for (int ni = 0; ni < 8; ni++) {
                const int col = n0 + wn + ni * 8 + 2 * t;
                const float2 bb = *(const float2*)(bias + e * N + col);
                float v0 = acc[mi][ni][0] + bb.x;
                float v1 = acc[mi][ni][1] + bb.y;
                float v2 = acc[mi][ni][2] + bb.x;
                float v3 = acc[mi][ni][3] + bb.y;
                if (FIRST) {
                    v0 = gelu(v0); v1 = gelu(v1); v2 = gelu(v2); v3 = gelu(v3);
                    uint32_t p0 = packlohi(v0, v1);
                    uint32_t p1 = packlohi(v2, v3);
                    if (row0 < mEnd)
                        *(uint32_t*)(g_hb + (size_t)row0 * HID + col) = p0;
                    if (row1 < mEnd)
                        *(uint32_t*)(g_hb + (size_t)row1 * HID + col) = p1;
                } else {
                    if (row0 < mEnd) {
                        float2 o = {v0, v1};
                        *(float2*)(g_o + (size_t)row0 * DIM + col) = o;
                    }
                    if (row1 < mEnd) {
                        float2 o = {v2, v3};
                        *(float2*)(g_o + (size_t)row1 * DIM + col) = o;
                    }
                }
            }
        }
        __syncthreads();   // cross-work hazard: next prologue rewrites stages
    }
}

// ---------------- combine: y = x + w0*o[s0] + w1*o[s1] ----------------------
__global__ void k_combine(const float* __restrict__ x, float* __restrict__ y,
                          int T) {
    int i = blockIdx.x * blockDim.x + threadIdx.x;
    int total = T * (DIM / 4);
    if (i >= total) return;
    int t = i / (DIM / 4);
    int d = (i - t * (DIM / 4)) * 4;
    float w0 = g_tw[2 * t], w1 = g_tw[2 * t + 1];
    int s0 = g_slot_of[2 * t], s1 = g_slot_of[2 * t + 1];
    float4 xv = *(const float4*)(x + (size_t)t * DIM + d);
    float4 o0 = *(const float4*)(g_o + (size_t)s0 * DIM + d);
    float4 o1 = *(const float4*)(g_o + (size_t)s1 * DIM + d);
    float4 r;
    r.x = xv.x + w0 * o0.x + w1 * o1.x;
    r.y = xv.y + w0 * o0.y + w1 * o1.y;
    r.z = xv.z + w0 * o0.z + w1 * o1.z;
    r.w = xv.w + w0 * o0.w + w1 * o1.w;
    *(float4*)(y + (size_t)t * DIM + d) = r;
}

// ---------------- launch -----------------------------------------------------
extern "C" void kernel_launch(void* const* d_in, const int* in_sizes, int n_in,
                              void* d_out, int out_size) {
    const float* x  = (const float*)d_in[0];
    const float* Wr = (const float*)d_in[1];
    const float* br = (const float*)d_in[2];
    const float* W1 = (const float*)d_in[3];
    const float* b1 = (const float*)d_in[4];
    const float* W2 = (const float*)d_in[5];
    const float* b2 = (const float*)d_in[6];
    float* y = (float*)d_out;
    const int T = in_sizes[0] / DIM;

    cudaFuncSetAttribute(k_gemm<true>,  cudaFuncAttributeMaxDynamicSharedMemorySize, GEMM_SMEM);
    cudaFuncSetAttribute(k_gemm<false>, cudaFuncAttributeMaxDynamicSharedMemorySize, GEMM_SMEM);

    __nv_bfloat16* w1p; cudaGetSymbolAddress((void**)&w1p, g_w1p);
    __nv_bfloat16* w2p; cudaGetSymbolAddress((void**)&w2p, g_w2p);
    __nv_bfloat16* xb;  cudaGetSymbolAddress((void**)&xb,  g_xb);

    k_init<<<1, 32>>>();
    {
        int tq1 = NE * (DIM / 2) * (HID / 4);
        k_cvtpair<<<(tq1 + 255) / 256, 256>>>(W1, w1p, DIM, HID);
        int tq2 = NE * (HID / 2) * (DIM / 4);
        k_cvtpair<<<(tq2 + 255) / 256, 256>>>(W2, w2p, HID, DIM);
        int x4 = T * DIM / 4;
        k_cvt<<<(x4 + 255) / 256, 256>>>(x, xb, x4);
    }
    k_router<<<(T + 31) / 32, 256>>>(x, Wr, br, T);
    k_scan<<<1, 32>>>();
    k_scatter<<<(2 * T + 255) / 256, 256>>>(T);

    k_gemm<true ><<<296, 256, GEMM_SMEM>>>(xb, w1p, b1);
    k_gemm<false><<<296, 256, GEMM_SMEM>>>(nullptr, w2p, b2);
    k_combine<<<(T * (DIM / 4) + 255) / 256, 256>>>(x, y, T);
}

// round 13
// speedup vs baseline: 2.0536x; 1.0276x over previous
#include <cuda_runtime.h>
#include <cuda_bf16.h>
#include <math.h>
#include <stdint.h>

#define NE 16
#define DIM 512
#define HID 1024
#define MAXT 8192
#define MAXSLOTS (MAXT * 2)

// ---------------- scratch (device globals; no allocation allowed) ----------
__device__ int   g_cnt[NE];
__device__ int   g_off[NE + 1];
__device__ int   g_tp[NE + 1];
__device__ int   g_tidx[MAXSLOTS];
__device__ int   g_rank[MAXSLOTS];
__device__ float g_tw[MAXSLOTS];
__device__ int   g_slot_token[MAXSLOTS];
__device__ int   g_slot_of[MAXSLOTS];
__device__ __nv_bfloat16 g_xb[(size_t)MAXT * DIM];       // x bf16 (same layout)
__device__ __nv_bfloat16 g_hb[(size_t)MAXSLOTS * HID];   // gelu(h) bf16
__device__ float         g_o [(size_t)MAXSLOTS * DIM];   // expert out fp32
// weights, k-pair packed: word(kp,n) = {lo=W[2kp][n], hi=W[2kp+1][n]} bf16x2
__device__ __nv_bfloat16 g_w1p[(size_t)NE * DIM * HID];  // [E][DIM/2][HID] words
__device__ __nv_bfloat16 g_w2p[(size_t)NE * HID * DIM];  // [E][HID/2][DIM] words

// ---------------- PTX helpers ------------------------------------------------
__device__ __forceinline__ uint32_t smem_u32(const void* p) {
    uint32_t a;
    asm("{ .reg .u64 t; cvta.to.shared.u64 t, %1; cvt.u32.u64 %0, t; }"
        : "=r"(a) : "l"(p));
    return a;
}

#define CP_ASYNC16(dst, src) \
    asm volatile("cp.async.cg.shared.global [%0], [%1], 16;" \
                 :: "r"(dst), "l"(src) : "memory")
#define CP_COMMIT() asm volatile("cp.async.commit_group;" ::: "memory")
#define CP_WAIT2()  asm volatile("cp.async.wait_group 2;"  ::: "memory")

#define MMA_BF16(c, a0, a1, a2, a3, b0, b1) \
    asm volatile("mma.sync.aligned.m16n8k16.row.col.f32.bf16.bf16.f32 " \
                 "{%0,%1,%2,%3}, {%4,%5,%6,%7}, {%8,%9}, {%0,%1,%2,%3};" \
                 : "+f"((c)[0]), "+f"((c)[1]), "+f"((c)[2]), "+f"((c)[3]) \
                 : "r"(a0), "r"(a1), "r"(a2), "r"(a3), "r"(b0), "r"(b1))

// pack {lo, hi} fp32 -> bf16x2 (src0 = hi, src1 = lo; verified rounds 7-12)
__device__ __forceinline__ uint32_t packlohi(float lo, float hi) {
    uint32_t d;
    asm("cvt.rn.bf16x2.f32 %0, %1, %2;" : "=r"(d) : "f"(hi), "f"(lo));
    return d;
}

// ---------------- small kernels ---------------------------------------------
__global__ void k_init() { if (threadIdx.x < NE) g_cnt[threadIdx.x] = 0; }

// router v5: Wr in smem; 32 tokens/block, 8 thr/token; stores rank from atomic.
__global__ void __launch_bounds__(256)
k_router(const float* __restrict__ x, const float* __restrict__ Wr,
         const float* __restrict__ br, int T) {
    __shared__ float wrs[DIM * 17];
    for (int i = threadIdx.x; i < DIM * NE; i += 256) {
        int d = i >> 4, e = i & 15;
        wrs[d * 17 + e] = Wr[i];
    }
    __syncthreads();

    const int lane = threadIdx.x & 31;
    const int w    = threadIdx.x >> 5;
    const int q    = lane & 7;
    const int tok  = blockIdx.x * 32 + w * 4 + (lane >> 3);
    const int tokc = min(tok, T - 1);

    float acc[NE];
#pragma unroll
    for (int e = 0; e < NE; e++) acc[e] = 0.f;

    const float* xr = x + (size_t)tokc * DIM;
#pragma unroll 4
    for (int i = 0; i < DIM / 8; i++) {
        const int d = i * 8 + q;
        const float xs = xr[d];
        const float* wrow = wrs + d * 17;
#pragma unroll
        for (int e = 0; e < NE; e++) acc[e] = fmaf(xs, wrow[e], acc[e]);
    }
#pragma unroll
    for (int off = 1; off <= 4; off <<= 1)
#pragma unroll
        for (int e = 0; e < NE; e++)
            acc[e] += __shfl_xor_sync(0xffffffffu, acc[e], off);

    if (q == 0 && tok < T) {
        float l[NE];
#pragma unroll
        for (int e = 0; e < NE; e++) l[e] = acc[e] + br[e];
        int b0 = 0; float l0 = l[0];
#pragma unroll
        for (int e = 1; e < NE; e++) if (l[e] > l0) { l0 = l[e]; b0 = e; }
        int b1 = -1; float l1 = -3.0e38f;
#pragma unroll
        for (int e = 0; e < NE; e++)
            if (e != b0 && l[e] > l1) { l1 = l[e]; b1 = e; }
        float w0 = 1.f / (1.f + expf(l1 - l0));
        g_tidx[2 * tok] = b0; g_tidx[2 * tok + 1] = b1;
        g_tw[2 * tok] = w0;   g_tw[2 * tok + 1] = 1.f - w0;
        g_rank[2 * tok]     = atomicAdd(&g_cnt[b0], 1);
        g_rank[2 * tok + 1] = atomicAdd(&g_cnt[b1], 1);
    }
}

__global__ void k_scan() {
    if (threadIdx.x == 0) {
        g_off[0] = 0; g_tp[0] = 0;
        for (int e = 0; e < NE; e++) {
            int c = g_cnt[e];
            g_off[e + 1] = g_off[e] + c;
            g_tp[e + 1] = g_tp[e] + (c + 127) / 128;
        }
    }
}

// scatter v2: no atomics (rank captured in router)
__global__ void k_scatter(int T) {
    int i = blockIdx.x * blockDim.x + threadIdx.x;
    if (i >= 2 * T) return;
    int pos = g_off[g_tidx[i]] + g_rank[i];
    g_slot_token[pos] = i >> 1;
    g_slot_of[i] = pos;
}

// elementwise fp32 -> bf16, SAME layout (verified; used for x)
__global__ void k_cvt(const float* __restrict__ W,
                      __nv_bfloat16* __restrict__ Wb, int n4) {
    int i = blockIdx.x * blockDim.x + threadIdx.x;
    if (i >= n4) return;
    float4 v = *(const float4*)(W + (size_t)i * 4);
    __nv_bfloat162 a = __floats2bfloat162_rn(v.x, v.y);
    __nv_bfloat162 b = __floats2bfloat162_rn(v.z, v.w);
    uint2 o;
    o.x = *(uint32_t*)&a;
    o.y = *(uint32_t*)&b;
    *(uint2*)(Wb + (size_t)i * 4) = o;
}

// weights: [E][KK][NN] fp32 -> k-pair packed words [E][KK/2][NN] bf16x2.
__global__ void k_cvtpair(const float* __restrict__ W,
                          __nv_bfloat16* __restrict__ Wp, int KK, int NN) {
    int i = blockIdx.x * blockDim.x + threadIdx.x;
    int nq4 = NN / 4;
    int total = NE * (KK / 2) * nq4;
    if (i >= total) return;
    int nq = i % nq4;
    int rest = i / nq4;
    int kp = rest % (KK / 2);
    int e  = rest / (KK / 2);
    const float* base = W + ((size_t)e * KK + 2 * kp) * NN + nq * 4;
    float4 r0 = *(const float4*)base;          // k even
    float4 r1 = *(const float4*)(base + NN);   // k odd
    uint4 o;
    o.x = packlohi(r0.x, r1.x);
    o.y = packlohi(r0.y, r1.y);
    o.z = packlohi(r0.z, r1.z);
    o.w = packlohi(r0.w, r1.w);
    *(uint4*)(Wp + (((size_t)e * (KK / 2) + kp) * NN + nq * 4) * 2) = o;
}

__device__ __forceinline__ float gelu(float v) {
    return 0.5f * v * (1.f + erff(v * 0.70710678118654752f));
}

// ---------------- grouped GEMM: bf16 m16n8k16, cross-work pipelined ---------
// FIRST: g_hb = bf16(gelu(gather(g_xb) @ W1 + b1)),  N=HID, K=DIM
// else : g_o  = g_hb @ W2 + b2,                      N=DIM, K=HID
// A stage: bf16, 128 x (16+4) words, stride 20 (80B rows; verified r9-12)
// B stage: pair-packed words, 16 x (128+8) words, stride 136 (verified r12)
// Next work item's 3 prologue stages are loaded during the current work's
// last 3 k-iters (stage index continues mod 4: KT % 4 == 0), so the pipeline
// never drains across tiles and the epilogue overlaps the next tile's loads.
#define A_W  (128 * 20)
#define B_W  (16 * 136)
#define ST_W (A_W + B_W)            // 4736 words
#define ST_B ((uint32_t)(ST_W * 4)) // 18944 bytes
#define GEMM_SMEM (4 * ST_W * 4)    // 75776 bytes

template <bool FIRST>
__global__ void __launch_bounds__(256, 2)
k_gemm(const __nv_bfloat16* __restrict__ Ab,
       const __nv_bfloat16* __restrict__ Bw,   // pair-packed words
       const float* __restrict__ bias) {
    constexpr int N   = FIRST ? HID : DIM;
    constexpr int K   = FIRST ? DIM : HID;
    constexpr int KT  = K / 32;                 // 16 or 32 (both % 4 == 0)
    constexpr int NT  = N / 128;

    extern __shared__ uint32_t dsw[];
    const uint32_t sb = smem_u32(dsw);

    const int tid  = threadIdx.x;
    const int lane = tid & 31;
    const int wid  = tid >> 5;
    const int wm   = (wid & 3) * 32;
    const int wn   = (wid >> 2) * 64;
    const int g    = lane >> 2;
    const int t    = lane & 3;

    const int total = g_tp[NE] * NT;
    int work = blockIdx.x;
    if (work >= total) return;

    // work descriptor
    auto desc = [&](int wk, int& m0, int& mEnd, int& n0, int& e,
                    const char*& Bep) {
        int mt = wk / NT;
        int nt = wk - mt * NT;
        e = 0;
        while (g_tp[e + 1] <= mt) e++;
        m0   = g_off[e] + (mt - g_tp[e]) * 128;
        mEnd = g_off[e + 1];
        n0   = nt * 128;
        Bep  = (const char*)Bw + ((size_t)e * (K / 2) * N + n0) * 4;
    };

    // loader (verified r12), parameterized by work descriptor
    auto load_tile = [&](int m0, int mEnd, const char* Bep, int kt, int s) {
        const uint32_t ab = sb + (uint32_t)s * ST_B;
        const uint32_t bb = ab + A_W * 4;
#pragma unroll
        for (int j = 0; j < 2; j++) {
            int idx = tid + j * 256;
            int row = idx >> 2, c = idx & 3;
            int rg = min(m0 + row, mEnd - 1);
            const char* src;
            if (FIRST)
                src = (const char*)g_xb
                    + ((size_t)g_slot_token[rg] * DIM + kt * 32) * 2 + c * 16;
            else
                src = (const char*)g_hb
                    + ((size_t)rg * HID + kt * 32) * 2 + c * 16;
            CP_ASYNC16(ab + (uint32_t)(row * 80 + c * 16), src);
        }
#pragma unroll
        for (int j = 0; j < 2; j++) {
            int idx = tid + j * 256;
            int row = idx >> 5, c = idx & 31;
            const char* src = Bep + ((size_t)(kt * 16 + row) * N) * 4 + c * 16;
            CP_ASYNC16(bb + (uint32_t)(row * 544 + c * 16), src);
        }
    };

    int m0, mEnd, n0, e;
    const char* Bep;
    desc(work, m0, mEnd, n0, e, Bep);

    // prologue for first work only
    load_tile(m0, mEnd, Bep, 0, 0); CP_COMMIT();
    load_tile(m0, mEnd, Bep, 1, 1); CP_COMMIT();
    load_tile(m0, mEnd, Bep, 2, 2); CP_COMMIT();

    for (;;) {
        const int nwork = work + gridDim.x;
        const bool has_next = nwork < total;
        int nm0, nmEnd, nn0, ne;
        const char* nBep;
        if (has_next) desc(nwork, nm0, nmEnd, nn0, ne, nBep);

        float acc[2][8][4];
#pragma unroll
        for (int mi = 0; mi < 2; mi++)
#pragma unroll
            for (int ni = 0; ni < 8; ni++)
#pragma unroll
                for (int q = 0; q < 4; q++) acc[mi][ni][q] = 0.f;

        for (int i = 0; i < KT; i++) {
            CP_WAIT2();
            __syncthreads();
            const int s = i & 3;
            const uint32_t* Aw = dsw + (size_t)s * ST_W;
            const uint32_t* Bs = Aw + A_W;
#pragma unroll
            for (int ks = 0; ks < 2; ks++) {
                uint32_t af[2][4];
#pragma unroll
                for (int mi = 0; mi < 2; mi++) {
                    const int r = wm + mi * 16 + g;
                    af[mi][0] = Aw[r * 20 + ks * 8 + t];
                    af[mi][1] = Aw[(r + 8) * 20 + ks * 8 + t];
                    af[mi][2] = Aw[r * 20 + ks * 8 + 4 + t];
                    af[mi][3] = Aw[(r + 8) * 20 + ks * 8 + 4 + t];
                }
                const int kp = ks * 8 + t;
#pragma unroll
                for (int ni = 0; ni < 8; ni++) {
                    const int cn = wn + ni * 8 + g;
                    uint32_t b0 = Bs[kp * 136 + cn];
                    uint32_t b1 = Bs[(kp + 4) * 136 + cn];
                    MMA_BF16(acc[0][ni], af[0][0], af[0][1], af[0][2], af[0][3], b0, b1);
                    MMA_BF16(acc[1][ni], af[1][0], af[1][1], af[1][2], af[1][3], b0, b1);
                }
            }
            if (i + 3 < KT)
                load_tile(m0, mEnd, Bep, i + 3, (i + 3) & 3);
            else if (has_next)
                load_tile(nm0, nmEnd, nBep, i + 3 - KT, (i + 3) & 3);
            CP_COMMIT();
        }

        // epilogue (verified r9-12) — overlaps next work's prologue cp.asyncs
#pragma unroll
        for (int mi = 0; mi < 2; mi++) {
            const int row0 = m0 + wm + mi * 16 + g;
            const int row1 = row0 + 8;
#pragma unroll
            for (int ni = 0; ni < 8; ni++) {
                const int col = n0 + wn + ni * 8 + 2 * t;
                const float2 bb = *(const float2*)(bias + e * N + col);
                float v0 = acc[mi][ni][0] + bb.x;
                float v1 = acc[mi][ni][1] + bb.y;
                float v2 = acc[mi][ni][2] + bb.x;
                float v3 = acc[mi][ni][3] + bb.y;
                if (FIRST) {
                    v0 = gelu(v0); v1 = gelu(v1); v2 = gelu(v2); v3 = gelu(v3);
                    uint32_t p0 = packlohi(v0, v1);
                    uint32_t p1 = packlohi(v2, v3);
                    if (row0 < mEnd)
                        *(uint32_t*)(g_hb + (size_t)row0 * HID + col) = p0;
                    if (row1 < mEnd)
                        *(uint32_t*)(g_hb + (size_t)row1 * HID + col) = p1;
                } else {
                    if (row0 < mEnd) {
                        float2 o = {v0, v1};
                        *(float2*)(g_o + (size_t)row0 * DIM + col) = o;
                    }
                    if (row1 < mEnd) {
                        float2 o = {v2, v3};
                        *(float2*)(g_o + (size_t)row1 * DIM + col) = o;
                    }
                }
            }
        }

        if (!has_next) break;
        work = nwork;
        m0 = nm0; mEnd = nmEnd; n0 = nn0; e = ne; Bep = nBep;
    }
}

// ---------------- combine: y = x + w0*o[s0] + w1*o[s1] ----------------------
__global__ void k_combine(const float* __restrict__ x, float* __restrict__ y,
                          int T) {
    int i = blockIdx.x * blockDim.x + threadIdx.x;
    int total = T * (DIM / 4);
    if (i >= total) return;
    int t = i / (DIM / 4);
    int d = (i - t * (DIM / 4)) * 4;
    float w0 = g_tw[2 * t], w1 = g_tw[2 * t + 1];
    int s0 = g_slot_of[2 * t], s1 = g_slot_of[2 * t + 1];
    float4 xv = *(const float4*)(x + (size_t)t * DIM + d);
    float4 o0 = *(const float4*)(g_o + (size_t)s0 * DIM + d);
    float4 o1 = *(const float4*)(g_o + (size_t)s1 * DIM + d);
    float4 r;
    r.x = xv.x + w0 * o0.x + w1 * o1.x;
    r.y = xv.y + w0 * o0.y + w1 * o1.y;
    r.z = xv.z + w0 * o0.z + w1 * o1.z;
    r.w = xv.w + w0 * o0.w + w1 * o1.w;
    *(float4*)(y + (size_t)t * DIM + d) = r;
}

// ---------------- launch -----------------------------------------------------
extern "C" void kernel_launch(void* const* d_in, const int* in_sizes, int n_in,
                              void* d_out, int out_size) {
    const float* x  = (const float*)d_in[0];
    const float* Wr = (const float*)d_in[1];
    const float* br = (const float*)d_in[2];
    const float* W1 = (const float*)d_in[3];
    const float* b1 = (const float*)d_in[4];
    const float* W2 = (const float*)d_in[5];
    const float* b2 = (const float*)d_in[6];
    float* y = (float*)d_out;
    const int T = in_sizes[0] / DIM;

    cudaFuncSetAttribute(k_gemm<true>,  cudaFuncAttributeMaxDynamicSharedMemorySize, GEMM_SMEM);
    cudaFuncSetAttribute(k_gemm<false>, cudaFuncAttributeMaxDynamicSharedMemorySize, GEMM_SMEM);

    __nv_bfloat16* w1p; cudaGetSymbolAddress((void**)&w1p, g_w1p);
    __nv_bfloat16* w2p; cudaGetSymbolAddress((void**)&w2p, g_w2p);
    __nv_bfloat16* xb;  cudaGetSymbolAddress((void**)&xb,  g_xb);

    k_init<<<1, 32>>>();
    {
        int tq1 = NE * (DIM / 2) * (HID / 4);
        k_cvtpair<<<(tq1 + 255) / 256, 256>>>(W1, w1p, DIM, HID);
        int tq2 = NE * (HID / 2) * (DIM / 4);
        k_cvtpair<<<(tq2 + 255) / 256, 256>>>(W2, w2p, HID, DIM);
        int x4 = T * DIM / 4;
        k_cvt<<<(x4 + 255) / 256, 256>>>(x, xb, x4);
    }
    k_router<<<(T + 31) / 32, 256>>>(x, Wr, br, T);
    k_scan<<<1, 32>>>();
    k_scatter<<<(2 * T + 255) / 256, 256>>>(T);

    k_gemm<true ><<<296, 256, GEMM_SMEM>>>(xb, w1p, b1);
    k_gemm<false><<<296, 256, GEMM_SMEM>>>(nullptr, w2p, b2);
    k_combine<<<(T * (DIM / 4) + 255) / 256, 256>>>(x, y, T);
}

// round 14
// speedup vs baseline: 2.0993x; 1.0223x over previous
#include <cuda_runtime.h>
#include <cuda_bf16.h>
#include <math.h>
#include <stdint.h>

#define NE 16
#define DIM 512
#define HID 1024
#define MAXT 8192
#define MAXSLOTS (MAXT * 2)

// ---------------- scratch (device globals; no allocation allowed) ----------
__device__ int   g_cnt[NE];
__device__ int   g_off[NE + 1];
__device__ int   g_tp[NE + 1];
__device__ int   g_tidx[MAXSLOTS];
__device__ int   g_rank[MAXSLOTS];
__device__ float g_tw[MAXSLOTS];
__device__ int   g_slot_token[MAXSLOTS];
__device__ float g_tws[MAXSLOTS];                        // weight per slot
__device__ __nv_bfloat16 g_xb[(size_t)MAXT * DIM];       // x bf16 (same layout)
__device__ __nv_bfloat16 g_hb[(size_t)MAXSLOTS * HID];   // gelu(h) bf16
// weights, k-pair packed: word(kp,n) = {lo=W[2kp][n], hi=W[2kp+1][n]} bf16x2
__device__ __nv_bfloat16 g_w1p[(size_t)NE * DIM * HID];  // [E][DIM/2][HID] words
__device__ __nv_bfloat16 g_w2p[(size_t)NE * HID * DIM];  // [E][HID/2][DIM] words

// ---------------- PTX helpers ------------------------------------------------
__device__ __forceinline__ uint32_t smem_u32(const void* p) {
    uint32_t a;
    asm("{ .reg .u64 t; cvta.to.shared.u64 t, %1; cvt.u32.u64 %0, t; }"
        : "=r"(a) : "l"(p));
    return a;
}

#define CP_ASYNC16(dst, src) \
    asm volatile("cp.async.cg.shared.global [%0], [%1], 16;" \
                 :: "r"(dst), "l"(src) : "memory")
#define CP_COMMIT() asm volatile("cp.async.commit_group;" ::: "memory")
#define CP_WAIT2()  asm volatile("cp.async.wait_group 2;"  ::: "memory")

#define MMA_BF16(c, a0, a1, a2, a3, b0, b1) \
    asm volatile("mma.sync.aligned.m16n8k16.row.col.f32.bf16.bf16.f32 " \
                 "{%0,%1,%2,%3}, {%4,%5,%6,%7}, {%8,%9}, {%0,%1,%2,%3};" \
                 : "+f"((c)[0]), "+f"((c)[1]), "+f"((c)[2]), "+f"((c)[3]) \
                 : "r"(a0), "r"(a1), "r"(a2), "r"(a3), "r"(b0), "r"(b1))

// pack {lo, hi} fp32 -> bf16x2 (src0 = hi, src1 = lo; verified rounds 7-13)
__device__ __forceinline__ uint32_t packlohi(float lo, float hi) {
    uint32_t d;
    asm("cvt.rn.bf16x2.f32 %0, %1, %2;" : "=r"(d) : "f"(hi), "f"(lo));
    return d;
}

// ---------------- small kernels ---------------------------------------------
__global__ void k_init() { if (threadIdx.x < NE) g_cnt[threadIdx.x] = 0; }

// router v5 (verified r13): Wr in smem; 32 tokens/block, 8 thr/token.
__global__ void __launch_bounds__(256)
k_router(const float* __restrict__ x, const float* __restrict__ Wr,
         const float* __restrict__ br, int T) {
    __shared__ float wrs[DIM * 17];
    for (int i = threadIdx.x; i < DIM * NE; i += 256) {
        int d = i >> 4, e = i & 15;
        wrs[d * 17 + e] = Wr[i];
    }
    __syncthreads();

    const int lane = threadIdx.x & 31;
    const int w    = threadIdx.x >> 5;
    const int q    = lane & 7;
    const int tok  = blockIdx.x * 32 + w * 4 + (lane >> 3);
    const int tokc = min(tok, T - 1);

    float acc[NE];
#pragma unroll
    for (int e = 0; e < NE; e++) acc[e] = 0.f;

    const float* xr = x + (size_t)tokc * DIM;
#pragma unroll 4
    for (int i = 0; i < DIM / 8; i++) {
        const int d = i * 8 + q;
        const float xs = xr[d];
        const float* wrow = wrs + d * 17;
#pragma unroll
        for (int e = 0; e < NE; e++) acc[e] = fmaf(xs, wrow[e], acc[e]);
    }
#pragma unroll
    for (int off = 1; off <= 4; off <<= 1)
#pragma unroll
        for (int e = 0; e < NE; e++)
            acc[e] += __shfl_xor_sync(0xffffffffu, acc[e], off);

    if (q == 0 && tok < T) {
        float l[NE];
#pragma unroll
        for (int e = 0; e < NE; e++) l[e] = acc[e] + br[e];
        int b0 = 0; float l0 = l[0];
#pragma unroll
        for (int e = 1; e < NE; e++) if (l[e] > l0) { l0 = l[e]; b0 = e; }
        int b1 = -1; float l1 = -3.0e38f;
#pragma unroll
        for (int e = 0; e < NE; e++)
            if (e != b0 && l[e] > l1) { l1 = l[e]; b1 = e; }
        float w0 = 1.f / (1.f + expf(l1 - l0));
        g_tidx[2 * tok] = b0; g_tidx[2 * tok + 1] = b1;
        g_tw[2 * tok] = w0;   g_tw[2 * tok + 1] = 1.f - w0;
        g_rank[2 * tok]     = atomicAdd(&g_cnt[b0], 1);
        g_rank[2 * tok + 1] = atomicAdd(&g_cnt[b1], 1);
    }
}

__global__ void k_scan() {
    if (threadIdx.x == 0) {
        g_off[0] = 0; g_tp[0] = 0;
        for (int e = 0; e < NE; e++) {
            int c = g_cnt[e];
            g_off[e + 1] = g_off[e] + c;
            g_tp[e + 1] = g_tp[e] + (c + 127) / 128;
        }
    }
}

// scatter v3: no atomics; also permutes the combine weight per slot
__global__ void k_scatter(int T) {
    int i = blockIdx.x * blockDim.x + threadIdx.x;
    if (i >= 2 * T) return;
    int pos = g_off[g_tidx[i]] + g_rank[i];
    g_slot_token[pos] = i >> 1;
    g_tws[pos]        = g_tw[i];
}

// merged prep: W1 pair-pack | W2 pair-pack | x -> (xb bf16, y = x copy)
// pair-pack (verified r12/13): word(e,kp,n) = {lo=bf16 W[e][2kp][n], hi=...[2kp+1][n]}
__device__ __forceinline__ void pairpack(const float* __restrict__ W,
                                         __nv_bfloat16* __restrict__ Wp,
                                         int KK, int NN, int i) {
    int nq4 = NN / 4;
    int nq = i % nq4;
    int rest = i / nq4;
    int kp = rest % (KK / 2);
    int e  = rest / (KK / 2);
    const float* base = W + ((size_t)e * KK + 2 * kp) * NN + nq * 4;
    float4 r0 = *(const float4*)base;
    float4 r1 = *(const float4*)(base + NN);
    uint4 o;
    o.x = packlohi(r0.x, r1.x);
    o.y = packlohi(r0.y, r1.y);
    o.z = packlohi(r0.z, r1.z);
    o.w = packlohi(r0.w, r1.w);
    *(uint4*)(Wp + (((size_t)e * (KK / 2) + kp) * NN + nq * 4) * 2) = o;
}

#define WSEG 4096   // blocks per weight segment: NE*(K/2)*(N/4)/256 = 4096

__global__ void __launch_bounds__(256)
k_prep(const float* __restrict__ W1, const float* __restrict__ W2,
       const float* __restrict__ x,
       __nv_bfloat16* __restrict__ w1p, __nv_bfloat16* __restrict__ w2p,
       __nv_bfloat16* __restrict__ xb, float* __restrict__ y, int T) {
    int b = blockIdx.x;
    if (b < WSEG) {
        pairpack(W1, w1p, DIM, HID, b * 256 + threadIdx.x);
    } else if (b < 2 * WSEG) {
        pairpack(W2, w2p, HID, DIM, (b - WSEG) * 256 + threadIdx.x);
    } else {
        int i = (b - 2 * WSEG) * 256 + threadIdx.x;
        if (i < T * (DIM / 4)) {
            float4 v = *(const float4*)(x + (size_t)i * 4);
            uint2 o;
            o.x = packlohi(v.x, v.y);
            o.y = packlohi(v.z, v.w);
            *(uint2*)(xb + (size_t)i * 4) = o;
            *(float4*)(y + (size_t)i * 4) = v;   // y init = x (residual)
        }
    }
}

__device__ __forceinline__ float gelu(float v) {
    return 0.5f * v * (1.f + erff(v * 0.70710678118654752f));
}

// ---------------- grouped GEMM: bf16 m16n8k16, cross-work pipelined ---------
// FIRST: g_hb = bf16(gelu(gather(g_xb) @ W1 + b1)),  N=HID, K=DIM
// else : y[tok] += w_slot * (g_hb @ W2 + b2)  (fused combine, fp32 atomics)
#define A_W  (128 * 20)
#define B_W  (16 * 136)
#define ST_W (A_W + B_W)            // 4736 words
#define ST_B ((uint32_t)(ST_W * 4)) // 18944 bytes
#define GEMM_SMEM (4 * ST_W * 4)    // 75776 bytes

template <bool FIRST>
__global__ void __launch_bounds__(256, 2)
k_gemm(const __nv_bfloat16* __restrict__ Bw,   // pair-packed words
       const float* __restrict__ bias,
       float* __restrict__ yout) {
    constexpr int N   = FIRST ? HID : DIM;
    constexpr int K   = FIRST ? DIM : HID;
    constexpr int KT  = K / 32;
    constexpr int NT  = N / 128;

    extern __shared__ uint32_t dsw[];
    const uint32_t sb = smem_u32(dsw);

    const int tid  = threadIdx.x;
    const int lane = tid & 31;
    const int wid  = tid >> 5;
    const int wm   = (wid & 3) * 32;
    const int wn   = (wid >> 2) * 64;
    const int g    = lane >> 2;
    const int t    = lane & 3;

    const int total = g_tp[NE] * NT;
    int work = blockIdx.x;
    if (work >= total) return;

    auto desc = [&](int wk, int& m0, int& mEnd, int& n0, int& e,
                    const char*& Bep) {
        int mt = wk / NT;
        int nt = wk - mt * NT;
        e = 0;
        while (g_tp[e + 1] <= mt) e++;
        m0   = g_off[e] + (mt - g_tp[e]) * 128;
        mEnd = g_off[e + 1];
        n0   = nt * 128;
        Bep  = (const char*)Bw + ((size_t)e * (K / 2) * N + n0) * 4;
    };

    auto load_tile = [&](int m0, int mEnd, const char* Bep, int kt, int s) {
        const uint32_t ab = sb + (uint32_t)s * ST_B;
        const uint32_t bb = ab + A_W * 4;
#pragma unroll
        for (int j = 0; j < 2; j++) {
            int idx = tid + j * 256;
            int row = idx >> 2, c = idx & 3;
            int rg = min(m0 + row, mEnd - 1);
            const char* src;
            if (FIRST)
                src = (const char*)g_xb
                    + ((size_t)g_slot_token[rg] * DIM + kt * 32) * 2 + c * 16;
            else
                src = (const char*)g_hb
                    + ((size_t)rg * HID + kt * 32) * 2 + c * 16;
            CP_ASYNC16(ab + (uint32_t)(row * 80 + c * 16), src);
        }
#pragma unroll
        for (int j = 0; j < 2; j++) {
            int idx = tid + j * 256;
            int row = idx >> 5, c = idx & 31;
            const char* src = Bep + ((size_t)(kt * 16 + row) * N) * 4 + c * 16;
            CP_ASYNC16(bb + (uint32_t)(row * 544 + c * 16), src);
        }
    };

    int m0, mEnd, n0, e;
    const char* Bep;
    desc(work, m0, mEnd, n0, e, Bep);

    load_tile(m0, mEnd, Bep, 0, 0); CP_COMMIT();
    load_tile(m0, mEnd, Bep, 1, 1); CP_COMMIT();
    load_tile(m0, mEnd, Bep, 2, 2); CP_COMMIT();

    for (;;) {
        const int nwork = work + gridDim.x;
        const bool has_next = nwork < total;
        int nm0, nmEnd, nn0, ne;
        const char* nBep;
        if (has_next) desc(nwork, nm0, nmEnd, nn0, ne, nBep);

        float acc[2][8][4];
#pragma unroll
        for (int mi = 0; mi < 2; mi++)
#pragma unroll
            for (int ni = 0; ni < 8; ni++)
#pragma unroll
                for (int q = 0; q < 4; q++) acc[mi][ni][q] = 0.f;

        for (int i = 0; i < KT; i++) {
            CP_WAIT2();
            __syncthreads();
            const int s = i & 3;
            const uint32_t* Aw = dsw + (size_t)s * ST_W;
            const uint32_t* Bs = Aw + A_W;
#pragma unroll
            for (int ks = 0; ks < 2; ks++) {
                uint32_t af[2][4];
#pragma unroll
                for (int mi = 0; mi < 2; mi++) {
                    const int r = wm + mi * 16 + g;
                    af[mi][0] = Aw[r * 20 + ks * 8 + t];
                    af[mi][1] = Aw[(r + 8) * 20 + ks * 8 + t];
                    af[mi][2] = Aw[r * 20 + ks * 8 + 4 + t];
                    af[mi][3] = Aw[(r + 8) * 20 + ks * 8 + 4 + t];
                }
                const int kp = ks * 8 + t;
#pragma unroll
                for (int ni = 0; ni < 8; ni++) {
                    const int cn = wn + ni * 8 + g;
                    uint32_t b0 = Bs[kp * 136 + cn];
                    uint32_t b1 = Bs[(kp + 4) * 136 + cn];
                    MMA_BF16(acc[0][ni], af[0][0], af[0][1], af[0][2], af[0][3], b0, b1);
                    MMA_BF16(acc[1][ni], af[1][0], af[1][1], af[1][2], af[1][3], b0, b1);
                }
            }
            if (i + 3 < KT)
                load_tile(m0, mEnd, Bep, i + 3, (i + 3) & 3);
            else if (has_next)
                load_tile(nm0, nmEnd, nBep, i + 3 - KT, (i + 3) & 3);
            CP_COMMIT();
        }

        // epilogue — overlaps next work's prologue cp.asyncs
#pragma unroll
        for (int mi = 0; mi < 2; mi++) {
            const int row0 = m0 + wm + mi * 16 + g;
            const int row1 = row0 + 8;
            // fused-combine metadata (GEMM2 only)
            int   tok0 = 0, tok1 = 0;
            float ws0 = 0.f, ws1 = 0.f;
            if (!FIRST) {
                if (row0 < mEnd) { tok0 = g_slot_token[row0]; ws0 = g_tws[row0]; }
                if (row1 < mEnd) { tok1 = g_slot_token[row1]; ws1 = g_tws[row1]; }
            }
#pragma unroll
            for (int ni = 0; ni < 8; ni++) {
                const int col = n0 + wn + ni * 8 + 2 * t;
                const float2 bb = *(const float2*)(bias + e * N + col);
                float v0 = acc[mi][ni][0] + bb.x;
                float v1 = acc[mi][ni][1] + bb.y;
                float v2 = acc[mi][ni][2] + bb.x;
                float v3 = acc[mi][ni][3] + bb.y;
                if (FIRST) {
                    v0 = gelu(v0); v1 = gelu(v1); v2 = gelu(v2); v3 = gelu(v3);
                    uint32_t p0 = packlohi(v0, v1);
                    uint32_t p1 = packlohi(v2, v3);
                    if (row0 < mEnd)
                        *(uint32_t*)(g_hb + (size_t)row0 * HID + col) = p0;
                    if (row1 < mEnd)
                        *(uint32_t*)(g_hb + (size_t)row1 * HID + col) = p1;
                } else {
                    if (row0 < mEnd) {
                        float* yp = yout + (size_t)tok0 * DIM + col;
                        atomicAdd(yp,     ws0 * v0);
                        atomicAdd(yp + 1, ws0 * v1);
                    }
                    if (row1 < mEnd) {
                        float* yp = yout + (size_t)tok1 * DIM + col;
                        atomicAdd(yp,     ws1 * v2);
                        atomicAdd(yp + 1, ws1 * v3);
                    }
                }
            }
        }

        if (!has_next) break;
        work = nwork;
        m0 = nm0; mEnd = nmEnd; n0 = nn0; e = ne; Bep = nBep;
    }
}

// ---------------- launch -----------------------------------------------------
extern "C" void kernel_launch(void* const* d_in, const int* in_sizes, int n_in,
                              void* d_out, int out_size) {
    const float* x  = (const float*)d_in[0];
    const float* Wr = (const float*)d_in[1];
    const float* br = (const float*)d_in[2];
    const float* W1 = (const float*)d_in[3];
    const float* b1 = (const float*)d_in[4];
    const float* W2 = (const float*)d_in[5];
    const float* b2 = (const float*)d_in[6];
    float* y = (float*)d_out;
    const int T = in_sizes[0] / DIM;

    cudaFuncSetAttribute(k_gemm<true>,  cudaFuncAttributeMaxDynamicSharedMemorySize, GEMM_SMEM);
    cudaFuncSetAttribute(k_gemm<false>, cudaFuncAttributeMaxDynamicSharedMemorySize, GEMM_SMEM);

    __nv_bfloat16* w1p; cudaGetSymbolAddress((void**)&w1p, g_w1p);
    __nv_bfloat16* w2p; cudaGetSymbolAddress((void**)&w2p, g_w2p);
    __nv_bfloat16* xb;  cudaGetSymbolAddress((void**)&xb,  g_xb);

    k_init<<<1, 32>>>();
    {
        int xblk = (T * (DIM / 4) + 255) / 256;
        k_prep<<<2 * WSEG + xblk, 256>>>(W1, W2, x, w1p, w2p, xb, y, T);
    }
    k_router<<<(T + 31) / 32, 256>>>(x, Wr, br, T);
    k_scan<<<1, 32>>>();
    k_scatter<<<(2 * T + 255) / 256, 256>>>(T);

    k_gemm<true ><<<296, 256, GEMM_SMEM>>>(w1p, b1, nullptr);
    k_gemm<false><<<296, 256, GEMM_SMEM>>>(w2p, b2, y);
}